// round 14
// baseline (speedup 1.0000x reference)
#include <cuda_runtime.h>
#include <cuda_bf16.h>
#include <math.h>
#include <stdint.h>

// Problem constants
#define S_LEN 2048
#define BATCH 2
#define DMODEL 1024
#define NH 16
#define DKH 64
#define MROWS (S_LEN * BATCH)   // 4096

// ---------------------------------------------------------------------------
// Scratch (allocation-free rule: __device__ globals). All split-bf16 pairs.
// ---------------------------------------------------------------------------
__device__ __nv_bfloat16 g_xh[(size_t)MROWS * DMODEL];
__device__ __nv_bfloat16 g_xl[(size_t)MROWS * DMODEL];
__device__ __nv_bfloat16 g_wqh[(size_t)3 * DMODEL * DMODEL];
__device__ __nv_bfloat16 g_wql[(size_t)3 * DMODEL * DMODEL];
__device__ __nv_bfloat16 g_woh[(size_t)DMODEL * DMODEL];
__device__ __nv_bfloat16 g_wol[(size_t)DMODEL * DMODEL];
__device__ __nv_bfloat16 g_qkvh[(size_t)MROWS * 3 * DMODEL];
__device__ __nv_bfloat16 g_qkvl[(size_t)MROWS * 3 * DMODEL];
__device__ __nv_bfloat16 g_ah[(size_t)MROWS * DMODEL];
__device__ __nv_bfloat16 g_al[(size_t)MROWS * DMODEL];

// ---------------------------------------------------------------------------
// Helpers
// ---------------------------------------------------------------------------
__device__ __forceinline__ uint32_t smem_u32(const void* p) {
    uint32_t a;
    asm("{ .reg .u64 t; cvta.to.shared.u64 t, %1; cvt.u32.u64 %0, t; }"
        : "=r"(a) : "l"(p));
    return a;
}

// split (x,y) -> packed bf16x2 hi + packed bf16x2 lo
__device__ __forceinline__ void bsplit2(float x, float y, uint32_t& hi, uint32_t& lo) {
    __nv_bfloat16 hx = __float2bfloat16(x);
    __nv_bfloat16 hy = __float2bfloat16(y);
    __nv_bfloat16 lx = __float2bfloat16(x - __bfloat162float(hx));
    __nv_bfloat16 ly = __float2bfloat16(y - __bfloat162float(hy));
    hi = (uint32_t)__bfloat16_as_ushort(hx) | ((uint32_t)__bfloat16_as_ushort(hy) << 16);
    lo = (uint32_t)__bfloat16_as_ushort(lx) | ((uint32_t)__bfloat16_as_ushort(ly) << 16);
}

// m16n8k16 bf16 mma, D (f32) += A * B
__device__ __forceinline__ void mma_bf16(float* d, const uint32_t* a,
                                         uint32_t b0, uint32_t b1) {
    asm volatile(
        "mma.sync.aligned.m16n8k16.row.col.f32.bf16.bf16.f32 "
        "{%0,%1,%2,%3},{%4,%5,%6,%7},{%8,%9},{%0,%1,%2,%3};"
        : "+f"(d[0]), "+f"(d[1]), "+f"(d[2]), "+f"(d[3])
        : "r"(a[0]), "r"(a[1]), "r"(a[2]), "r"(a[3]), "r"(b0), "r"(b1));
}

__device__ __forceinline__ void ldm_x4(uint32_t* r, uint32_t addr) {
    asm volatile(
        "ldmatrix.sync.aligned.m8n8.x4.shared.b16 {%0,%1,%2,%3}, [%4];"
        : "=r"(r[0]), "=r"(r[1]), "=r"(r[2]), "=r"(r[3]) : "r"(addr));
}
__device__ __forceinline__ void ldm_x2(uint32_t* r, uint32_t addr) {
    asm volatile(
        "ldmatrix.sync.aligned.m8n8.x2.shared.b16 {%0,%1}, [%2];"
        : "=r"(r[0]), "=r"(r[1]) : "r"(addr));
}
__device__ __forceinline__ void ldm_x2t(uint32_t* r, uint32_t addr) {
    asm volatile(
        "ldmatrix.sync.aligned.m8n8.x2.trans.shared.b16 {%0,%1}, [%2];"
        : "=r"(r[0]), "=r"(r[1]) : "r"(addr));
}

__device__ __forceinline__ void cpasync16(uint32_t dst, const void* src) {
    asm volatile("cp.async.cg.shared.global [%0], [%1], 16;" :: "r"(dst), "l"(src));
}
__device__ __forceinline__ void cp_commit() {
    asm volatile("cp.async.commit_group;" ::: "memory");
}
template<int N> __device__ __forceinline__ void cp_wait() {
    asm volatile("cp.async.wait_group %0;" :: "n"(N) : "memory");
}

// ---------------------------------------------------------------------------
// Kernel: elementwise split fp32 -> bf16 hi/lo
// ---------------------------------------------------------------------------
__global__ __launch_bounds__(256) void split_kernel(
    const float* __restrict__ in, __nv_bfloat16* __restrict__ h,
    __nv_bfloat16* __restrict__ l, int n)
{
    int i4 = (blockIdx.x * 256 + threadIdx.x) * 4;
    if (i4 >= n) return;
    float4 v = *(const float4*)(in + i4);
    uint32_t h0, l0, h1, l1;
    bsplit2(v.x, v.y, h0, l0);
    bsplit2(v.z, v.w, h1, l1);
    *(uint2*)((char*)h + (size_t)i4 * 2) = make_uint2(h0, h1);
    *(uint2*)((char*)l + (size_t)i4 * 2) = make_uint2(l0, l1);
}

// ---------------------------------------------------------------------------
// bf16-split GEMM: C[m,n] = sum_k A[m,k]*B[n,k] (+bias)
// BM=128, BN=32, BK=16, 128 threads (4 warps, warp tile 32x32).
// 3-stage cp.async, ldmatrix frags, 1 sync/iter, 4 CTAs/SM (16 warps/SM).
// Rows in smem: 16 bf16 (32B) + 16B pad = 48B stride (ldmatrix conflict-free).
// Stage: Ah@0 (6144) | Al@6144 | Bh@12288 (1536) | Bl@13824.  15360B/stage.
// ---------------------------------------------------------------------------
#define G_STAGE_BYTES 15360
#define G_SMEM_BYTES (3 * G_STAGE_BYTES)   // 46080

__global__ __launch_bounds__(128, 4) void gemm_bf16x3(
    const __nv_bfloat16* __restrict__ Ah, const __nv_bfloat16* __restrict__ Al,
    const __nv_bfloat16* __restrict__ Bh, const __nv_bfloat16* __restrict__ Bl,
    const float* __restrict__ bias, float* __restrict__ Cf,
    __nv_bfloat16* __restrict__ Ch, __nv_bfloat16* __restrict__ Cl,
    int M, int N, int K, int qscaleCols)
{
    extern __shared__ char smem[];
    const uint32_t sbase = smem_u32(smem);
    const int tid  = threadIdx.x;
    const int lane = tid & 31;
    const int warp = tid >> 5;        // 0..3, 32 rows each
    const int g    = lane >> 2;
    const int q4   = lane & 3;
    const int mBase = blockIdx.y * 128;
    const int nBase = blockIdx.x * 32;

    float acc[2][4][4];
#pragma unroll
    for (int i = 0; i < 2; ++i)
#pragma unroll
        for (int j = 0; j < 4; ++j)
#pragma unroll
            for (int c = 0; c < 4; ++c) acc[i][j][c] = 0.f;

    const int lj = lane >> 3, l7 = lane & 7;
    const uint32_t aRowBase = (uint32_t)(warp * 32 + (lj & 1) * 8 + l7) * 48
                              + (uint32_t)(lj >> 1) * 16;
    const uint32_t bRowBase = (uint32_t)((lj >> 1) * 8 + l7) * 48
                              + (uint32_t)(lj & 1) * 16;

    const int NT = K / 16;            // 64

    // gmem base pointers
    const char* ApA = (const char*)(Ah + (size_t)(mBase + tid) * K);
    const char* ApL = (const char*)(Al + (size_t)(mBase + tid) * K);
    const int bRow = tid >> 1, bCh = tid & 1;   // threads 0..63 load B
    const char* BpH = (const char*)(Bh + (size_t)(nBase + bRow) * K) + bCh * 16;
    const char* BpL = (const char*)(Bl + (size_t)(nBase + bRow) * K) + bCh * 16;

#define G_ISSUE(ITER) do {                                                      \
    int s_ = (ITER) % 3;                                                        \
    int kb_ = (ITER) * 32;  /* byte offset along K */                           \
    uint32_t stb_ = sbase + s_ * G_STAGE_BYTES;                                 \
    _Pragma("unroll")                                                           \
    for (int j_ = 0; j_ < 2; ++j_) {                                            \
        cpasync16(stb_ + tid * 48 + j_ * 16, ApA + kb_ + j_ * 16);              \
        cpasync16(stb_ + 6144 + tid * 48 + j_ * 16, ApL + kb_ + j_ * 16);       \
    }                                                                           \
    if (tid < 64) {                                                             \
        cpasync16(stb_ + 12288 + bRow * 48 + bCh * 16, BpH + kb_);              \
        cpasync16(stb_ + 13824 + bRow * 48 + bCh * 16, BpL + kb_);              \
    }                                                                           \
} while (0)

    G_ISSUE(0); cp_commit();
    G_ISSUE(1); cp_commit();

    for (int it = 0; it < NT; ++it) {
        if (it + 1 < NT) cp_wait<1>(); else cp_wait<0>();
        __syncthreads();
        if (it + 2 < NT) { G_ISSUE(it + 2); cp_commit(); }

        const uint32_t stb = sbase + (it % 3) * G_STAGE_BYTES;

        uint32_t ah[2][4], al[2][4];
#pragma unroll
        for (int mf = 0; mf < 2; ++mf) {
            ldm_x4(ah[mf], stb + aRowBase + mf * (16 * 48));
            ldm_x4(al[mf], stb + 6144 + aRowBase + mf * (16 * 48));
        }
        uint32_t bh[4][2], bl[4][2];
#pragma unroll
        for (int np = 0; np < 2; ++np) {
            uint32_t r[4];
            ldm_x4(r, stb + 12288 + bRowBase + np * (16 * 48));
            bh[np * 2][0] = r[0]; bh[np * 2][1] = r[1];
            bh[np * 2 + 1][0] = r[2]; bh[np * 2 + 1][1] = r[3];
            ldm_x4(r, stb + 13824 + bRowBase + np * (16 * 48));
            bl[np * 2][0] = r[0]; bl[np * 2][1] = r[1];
            bl[np * 2 + 1][0] = r[2]; bl[np * 2 + 1][1] = r[3];
        }
        // de-chained 3-term sweeps (acc reuse distance = 8 mmas)
#pragma unroll
        for (int mf = 0; mf < 2; ++mf)
#pragma unroll
            for (int nf = 0; nf < 4; ++nf)
                mma_bf16(acc[mf][nf], ah[mf], bh[nf][0], bh[nf][1]);
#pragma unroll
        for (int mf = 0; mf < 2; ++mf)
#pragma unroll
            for (int nf = 0; nf < 4; ++nf)
                mma_bf16(acc[mf][nf], ah[mf], bl[nf][0], bl[nf][1]);
#pragma unroll
        for (int mf = 0; mf < 2; ++mf)
#pragma unroll
            for (int nf = 0; nf < 4; ++nf)
                mma_bf16(acc[mf][nf], al[mf], bh[nf][0], bh[nf][1]);
    }
#undef G_ISSUE

    // Epilogue
    const int Np = N >> 1;
#pragma unroll
    for (int mf = 0; mf < 2; ++mf) {
        int r0 = mBase + warp * 32 + mf * 16 + g;
        int r1 = r0 + 8;
#pragma unroll
        for (int nf = 0; nf < 4; ++nf) {
            int col = nBase + nf * 8 + 2 * q4;
            if (Cf) {
                float bx = bias ? bias[col] : 0.f;
                float by = bias ? bias[col + 1] : 0.f;
                *(float2*)(Cf + (size_t)r0 * N + col) =
                    make_float2(acc[mf][nf][0] + bx, acc[mf][nf][1] + by);
                *(float2*)(Cf + (size_t)r1 * N + col) =
                    make_float2(acc[mf][nf][2] + bx, acc[mf][nf][3] + by);
            } else {
                float sc = (col < qscaleCols) ? 0.125f : 1.f;
                uint32_t hi, lo;
                bsplit2(acc[mf][nf][0] * sc, acc[mf][nf][1] * sc, hi, lo);
                ((uint32_t*)Ch)[(size_t)r0 * Np + (col >> 1)] = hi;
                ((uint32_t*)Cl)[(size_t)r0 * Np + (col >> 1)] = lo;
                bsplit2(acc[mf][nf][2] * sc, acc[mf][nf][3] * sc, hi, lo);
                ((uint32_t*)Ch)[(size_t)r1 * Np + (col >> 1)] = hi;
                ((uint32_t*)Cl)[(size_t)r1 * Np + (col >> 1)] = lo;
            }
        }
    }
}

// ---------------------------------------------------------------------------
// Flash attention, bf16-split mma (m16n8k16), 2-stage cp.async KV pipeline.
// grid (S/64, B*H), 128 threads (4 warps x 16 q rows). Q pre-scaled by 0.125.
// qt DESCENDING. P stays in registers. K: ldmatrix.x2; V: ldmatrix.x2.trans.
// ---------------------------------------------------------------------------
#define A_QL 2304
#define A_ST 4608
#define A_STAGE_U32 9216
#define ATT_SMEM_BYTES ((A_ST + 2 * A_STAGE_U32) * 4)   // 92160

__global__ __launch_bounds__(128) void attn_bf16(
    const __nv_bfloat16* __restrict__ QKVh, const __nv_bfloat16* __restrict__ QKVl,
    __nv_bfloat16* __restrict__ Oh, __nv_bfloat16* __restrict__ Ol)
{
    extern __shared__ uint32_t sm4[];
    const uint32_t sbase = smem_u32(sm4);
    const int qt  = gridDim.x - 1 - blockIdx.x;   // heavy tiles first
    const int bh  = blockIdx.y;
    const int h   = bh & 15;
    const int b   = bh >> 4;
    const int tid = threadIdx.x;
    const int w    = tid >> 5;
    const int lane = tid & 31;
    const int g    = lane >> 2;
    const int q4   = lane & 3;
    const int qBase = qt * 64;

#define KV_ISSUE(KT) do {                                                       \
    int s_ = (KT) & 1;                                                          \
    uint32_t stb_ = sbase + (A_ST + s_ * A_STAGE_U32) * 4;                      \
    _Pragma("unroll")                                                           \
    for (int j_ = 0; j_ < 4; ++j_) {                                            \
        int id_ = tid + j_ * 128;                                               \
        int row_ = id_ >> 3, ch_ = id_ & 7;                                     \
        size_t ks_ = (size_t)(((KT) * 64 + row_) * BATCH + b) * (3 * DMODEL)    \
                     + DMODEL + h * DKH;                                        \
        size_t vs_ = ks_ + DMODEL;                                              \
        cpasync16(stb_ + row_ * 144 + ch_ * 16, (const char*)(QKVh + ks_) + ch_ * 16); \
        cpasync16(stb_ + 9216 + row_ * 144 + ch_ * 16, (const char*)(QKVl + ks_) + ch_ * 16); \
        cpasync16(stb_ + 18432 + row_ * 144 + ch_ * 16, (const char*)(QKVh + vs_) + ch_ * 16); \
        cpasync16(stb_ + 27648 + row_ * 144 + ch_ * 16, (const char*)(QKVl + vs_) + ch_ * 16); \
    }                                                                           \
} while (0)

    KV_ISSUE(0); cp_commit();

    // Load Q tile (split, already scaled): 64 rows x 128B per array
#pragma unroll
    for (int j = 0; j < 4; ++j) {
        int id = tid + j * 128;
        int row = id >> 3, ch = id & 7;
        size_t src = (size_t)((qBase + row) * BATCH + b) * (3 * DMODEL) + h * DKH;
        uint4 vh = *(const uint4*)((const char*)(QKVh + src) + ch * 16);
        uint4 vl = *(const uint4*)((const char*)(QKVl + src) + ch * 16);
        *(uint4*)((char*)sm4 + row * 144 + ch * 16) = vh;
        *(uint4*)((char*)sm4 + A_QL * 4 + row * 144 + ch * 16) = vl;
    }
    __syncthreads();

    // Q fragments
    uint32_t qh[4][4], ql[4][4];
    {
        int r0 = (w * 16 + g) * 36;
        int r1 = r0 + 288;
#pragma unroll
        for (int kc = 0; kc < 4; ++kc) {
            qh[kc][0] = sm4[r0 + kc * 8 + q4];
            qh[kc][1] = sm4[r1 + kc * 8 + q4];
            qh[kc][2] = sm4[r0 + kc * 8 + 4 + q4];
            qh[kc][3] = sm4[r1 + kc * 8 + 4 + q4];
            ql[kc][0] = sm4[A_QL + r0 + kc * 8 + q4];
            ql[kc][1] = sm4[A_QL + r1 + kc * 8 + q4];
            ql[kc][2] = sm4[A_QL + r0 + kc * 8 + 4 + q4];
            ql[kc][3] = sm4[A_QL + r1 + kc * 8 + 4 + q4];
        }
    }

    float ofr[8][4];
#pragma unroll
    for (int nt = 0; nt < 8; ++nt)
#pragma unroll
        for (int c = 0; c < 4; ++c) ofr[nt][c] = 0.f;

    float m0 = -INFINITY, m1 = -INFINITY, l0 = 0.f, l1 = 0.f;
    const int qrow0 = qBase + w * 16 + g;
    const int qrow1 = qrow0 + 8;

    // ldmatrix per-lane address terms
    const int l7  = lane & 7;
    const int l15 = lane & 15;
    const uint32_t kLane = (uint32_t)l7 * 144 + (uint32_t)((lane >> 3) & 1) * 16;
    const uint32_t vLane = (uint32_t)l15 * 144;

    for (int kt = 0; kt <= qt; ++kt) {
        cp_wait<0>();
        __syncthreads();
        if (kt < qt) { KV_ISSUE(kt + 1); cp_commit(); }

        const uint32_t stb = sbase + (A_ST + (kt & 1) * A_STAGE_U32) * 4;
        const uint32_t stbKH = stb + kLane;
        const uint32_t stbKL = stbKH + 9216;
        const uint32_t stbVH = stb + 18432 + vLane;
        const uint32_t stbVL = stbVH + 9216;

        // S = Q K^T (3 de-chained sweeps per kc)
        float sfr[8][4];
#pragma unroll
        for (int nt = 0; nt < 8; ++nt)
#pragma unroll
            for (int c = 0; c < 4; ++c) sfr[nt][c] = 0.f;

#pragma unroll
        for (int kc = 0; kc < 4; ++kc) {
            uint32_t kh2[8][2], kl2[8][2];
#pragma unroll
            for (int nt = 0; nt < 8; ++nt) {
                ldm_x2(kh2[nt], stbKH + nt * (8 * 144) + kc * 32);
                ldm_x2(kl2[nt], stbKL + nt * (8 * 144) + kc * 32);
            }
#pragma unroll
            for (int nt = 0; nt < 8; ++nt)
                mma_bf16(sfr[nt], qh[kc], kh2[nt][0], kh2[nt][1]);
#pragma unroll
            for (int nt = 0; nt < 8; ++nt)
                mma_bf16(sfr[nt], qh[kc], kl2[nt][0], kl2[nt][1]);
#pragma unroll
            for (int nt = 0; nt < 8; ++nt)
                mma_bf16(sfr[nt], ql[kc], kh2[nt][0], kh2[nt][1]);
        }

        // Causal mask (diagonal tile only)
        if (kt == qt) {
#pragma unroll
            for (int nt = 0; nt < 8; ++nt) {
                int key = kt * 64 + nt * 8 + 2 * q4;
                if (key     > qrow0) sfr[nt][0] = -INFINITY;
                if (key + 1 > qrow0) sfr[nt][1] = -INFINITY;
                if (key     > qrow1) sfr[nt][2] = -INFINITY;
                if (key + 1 > qrow1) sfr[nt][3] = -INFINITY;
            }
        }

        // Online softmax
        float mx0 = -INFINITY, mx1 = -INFINITY;
#pragma unroll
        for (int nt = 0; nt < 8; ++nt) {
            mx0 = fmaxf(mx0, fmaxf(sfr[nt][0], sfr[nt][1]));
            mx1 = fmaxf(mx1, fmaxf(sfr[nt][2], sfr[nt][3]));
        }
        mx0 = fmaxf(mx0, __shfl_xor_sync(0xffffffffu, mx0, 1));
        mx0 = fmaxf(mx0, __shfl_xor_sync(0xffffffffu, mx0, 2));
        mx1 = fmaxf(mx1, __shfl_xor_sync(0xffffffffu, mx1, 1));
        mx1 = fmaxf(mx1, __shfl_xor_sync(0xffffffffu, mx1, 2));

        float mn0 = fmaxf(m0, mx0), mn1 = fmaxf(m1, mx1);
        float cr0 = __expf(m0 - mn0), cr1 = __expf(m1 - mn1);
        l0 *= cr0; l1 *= cr1;
        m0 = mn0;  m1 = mn1;

        // exp -> P fragments directly in registers
        uint32_t aph[8][2], apl[8][2];
        float ps0 = 0.f, ps1 = 0.f;
#pragma unroll
        for (int nt = 0; nt < 8; ++nt) {
            ofr[nt][0] *= cr0; ofr[nt][1] *= cr0;
            ofr[nt][2] *= cr1; ofr[nt][3] *= cr1;
            float p0 = __expf(sfr[nt][0] - m0);
            float p1 = __expf(sfr[nt][1] - m0);
            float p2 = __expf(sfr[nt][2] - m1);
            float p3 = __expf(sfr[nt][3] - m1);
            ps0 += p0 + p1; ps1 += p2 + p3;
            bsplit2(p0, p1, aph[nt][0], apl[nt][0]);
            bsplit2(p2, p3, aph[nt][1], apl[nt][1]);
        }
        ps0 += __shfl_xor_sync(0xffffffffu, ps0, 1);
        ps0 += __shfl_xor_sync(0xffffffffu, ps0, 2);
        ps1 += __shfl_xor_sync(0xffffffffu, ps1, 1);
        ps1 += __shfl_xor_sync(0xffffffffu, ps1, 2);
        l0 += ps0; l1 += ps1;

        // O += P V  (V fragments via ldmatrix.trans on K-major V rows)
#pragma unroll
        for (int kc = 0; kc < 4; ++kc) {
            uint32_t pah[4] = {aph[2 * kc][0], aph[2 * kc][1],
                               aph[2 * kc + 1][0], aph[2 * kc + 1][1]};
            uint32_t pal[4] = {apl[2 * kc][0], apl[2 * kc][1],
                               apl[2 * kc + 1][0], apl[2 * kc + 1][1]};
            uint32_t vh2[8][2], vl2[8][2];
#pragma unroll
            for (int nt = 0; nt < 8; ++nt) {
                ldm_x2t(vh2[nt], stbVH + kc * (16 * 144) + nt * 16);
                ldm_x2t(vl2[nt], stbVL + kc * (16 * 144) + nt * 16);
            }
#pragma unroll
            for (int nt = 0; nt < 8; ++nt)
                mma_bf16(ofr[nt], pah, vh2[nt][0], vh2[nt][1]);
#pragma unroll
            for (int nt = 0; nt < 8; ++nt)
                mma_bf16(ofr[nt], pah, vl2[nt][0], vl2[nt][1]);
#pragma unroll
            for (int nt = 0; nt < 8; ++nt)
                mma_bf16(ofr[nt], pal, vh2[nt][0], vh2[nt][1]);
        }
    }
#undef KV_ISSUE

    // Epilogue: normalize, split-write attention output
    float inv0 = 1.f / l0, inv1 = 1.f / l1;
    size_t row0 = (size_t)(qrow0 * BATCH + b) * (DMODEL / 2);
    size_t row1 = (size_t)(qrow1 * BATCH + b) * (DMODEL / 2);
#pragma unroll
    for (int nt = 0; nt < 8; ++nt) {
        int pcol = h * 32 + nt * 4 + q4;
        uint32_t hi, lo;
        bsplit2(ofr[nt][0] * inv0, ofr[nt][1] * inv0, hi, lo);
        ((uint32_t*)Oh)[row0 + pcol] = hi;
        ((uint32_t*)Ol)[row0 + pcol] = lo;
        bsplit2(ofr[nt][2] * inv1, ofr[nt][3] * inv1, hi, lo);
        ((uint32_t*)Oh)[row1 + pcol] = hi;
        ((uint32_t*)Ol)[row1 + pcol] = lo;
    }
}

// ---------------------------------------------------------------------------
extern "C" void kernel_launch(void* const* d_in, const int* in_sizes, int n_in,
                              void* d_out, int out_size)
{
    const float* x     = (const float*)d_in[0];   // [S,B,D]
    const float* w_qkv = (const float*)d_in[1];   // [3D,D]
    const float* w_out = (const float*)d_in[2];   // [D,D]
    const float* b_out = (const float*)d_in[3];   // [D]
    float* out = (float*)d_out;

    __nv_bfloat16 *xh, *xl, *wqh, *wql, *woh, *wol, *qkvh, *qkvl, *ah, *al;
    cudaGetSymbolAddress((void**)&xh,   g_xh);
    cudaGetSymbolAddress((void**)&xl,   g_xl);
    cudaGetSymbolAddress((void**)&wqh,  g_wqh);
    cudaGetSymbolAddress((void**)&wql,  g_wql);
    cudaGetSymbolAddress((void**)&woh,  g_woh);
    cudaGetSymbolAddress((void**)&wol,  g_wol);
    cudaGetSymbolAddress((void**)&qkvh, g_qkvh);
    cudaGetSymbolAddress((void**)&qkvl, g_qkvl);
    cudaGetSymbolAddress((void**)&ah,   g_ah);
    cudaGetSymbolAddress((void**)&al,   g_al);

    cudaFuncSetAttribute(gemm_bf16x3,
                         cudaFuncAttributeMaxDynamicSharedMemorySize, G_SMEM_BYTES);
    cudaFuncSetAttribute(attn_bf16,
                         cudaFuncAttributeMaxDynamicSharedMemorySize, ATT_SMEM_BYTES);

    // 0) Split inputs to bf16 hi/lo
    {
        int n1 = MROWS * DMODEL;        // x
        int n2 = 3 * DMODEL * DMODEL;   // w_qkv
        int n3 = DMODEL * DMODEL;       // w_out
        split_kernel<<<(n1 / 4 + 255) / 256, 256>>>(x, xh, xl, n1);
        split_kernel<<<(n2 / 4 + 255) / 256, 256>>>(w_qkv, wqh, wql, n2);
        split_kernel<<<(n3 / 4 + 255) / 256, 256>>>(w_out, woh, wol, n3);
    }

    // 1) QKV projection -> split qkv (Q cols scaled by 0.125)
    gemm_bf16x3<<<dim3(3 * DMODEL / 32, MROWS / 128), 128, G_SMEM_BYTES>>>(
        xh, xl, wqh, wql, nullptr, nullptr, qkvh, qkvl,
        MROWS, 3 * DMODEL, DMODEL, DMODEL);

    // 2) Causal flash attention -> split attention output
    attn_bf16<<<dim3(S_LEN / 64, BATCH * NH), 128, ATT_SMEM_BYTES>>>(
        qkvh, qkvl, ah, al);

    // 3) Output projection + bias -> fp32 out
    gemm_bf16x3<<<dim3(DMODEL / 32, MROWS / 128), 128, G_SMEM_BYTES>>>(
        ah, al, woh, wol, b_out, out, nullptr, nullptr,
        MROWS, DMODEL, DMODEL, 0);
}

// round 15
// speedup vs baseline: 1.3902x; 1.3902x over previous
#include <cuda_runtime.h>
#include <cuda_bf16.h>
#include <math.h>
#include <stdint.h>

// Problem constants
#define S_LEN 2048
#define BATCH 2
#define DMODEL 1024
#define NH 16
#define DKH 64
#define MROWS (S_LEN * BATCH)   // 4096

// ---------------------------------------------------------------------------
// Scratch (allocation-free rule: __device__ globals). All split-bf16 pairs.
// ---------------------------------------------------------------------------
__device__ __nv_bfloat16 g_xh[(size_t)MROWS * DMODEL];
__device__ __nv_bfloat16 g_xl[(size_t)MROWS * DMODEL];
__device__ __nv_bfloat16 g_wqh[(size_t)3 * DMODEL * DMODEL];
__device__ __nv_bfloat16 g_wql[(size_t)3 * DMODEL * DMODEL];
__device__ __nv_bfloat16 g_woh[(size_t)DMODEL * DMODEL];
__device__ __nv_bfloat16 g_wol[(size_t)DMODEL * DMODEL];
__device__ __nv_bfloat16 g_qkvh[(size_t)MROWS * 3 * DMODEL];
__device__ __nv_bfloat16 g_qkvl[(size_t)MROWS * 3 * DMODEL];
__device__ __nv_bfloat16 g_ah[(size_t)MROWS * DMODEL];
__device__ __nv_bfloat16 g_al[(size_t)MROWS * DMODEL];

// ---------------------------------------------------------------------------
// Helpers
// ---------------------------------------------------------------------------
__device__ __forceinline__ uint32_t smem_u32(const void* p) {
    uint32_t a;
    asm("{ .reg .u64 t; cvta.to.shared.u64 t, %1; cvt.u32.u64 %0, t; }"
        : "=r"(a) : "l"(p));
    return a;
}

// split (x,y) -> packed bf16x2 hi + packed bf16x2 lo
__device__ __forceinline__ void bsplit2(float x, float y, uint32_t& hi, uint32_t& lo) {
    __nv_bfloat16 hx = __float2bfloat16(x);
    __nv_bfloat16 hy = __float2bfloat16(y);
    __nv_bfloat16 lx = __float2bfloat16(x - __bfloat162float(hx));
    __nv_bfloat16 ly = __float2bfloat16(y - __bfloat162float(hy));
    hi = (uint32_t)__bfloat16_as_ushort(hx) | ((uint32_t)__bfloat16_as_ushort(hy) << 16);
    lo = (uint32_t)__bfloat16_as_ushort(lx) | ((uint32_t)__bfloat16_as_ushort(ly) << 16);
}

// m16n8k16 bf16 mma, D (f32) += A * B
__device__ __forceinline__ void mma_bf16(float* d, const uint32_t* a,
                                         uint32_t b0, uint32_t b1) {
    asm volatile(
        "mma.sync.aligned.m16n8k16.row.col.f32.bf16.bf16.f32 "
        "{%0,%1,%2,%3},{%4,%5,%6,%7},{%8,%9},{%0,%1,%2,%3};"
        : "+f"(d[0]), "+f"(d[1]), "+f"(d[2]), "+f"(d[3])
        : "r"(a[0]), "r"(a[1]), "r"(a[2]), "r"(a[3]), "r"(b0), "r"(b1));
}

__device__ __forceinline__ void ldm_x4(uint32_t* r, uint32_t addr) {
    asm volatile(
        "ldmatrix.sync.aligned.m8n8.x4.shared.b16 {%0,%1,%2,%3}, [%4];"
        : "=r"(r[0]), "=r"(r[1]), "=r"(r[2]), "=r"(r[3]) : "r"(addr));
}
__device__ __forceinline__ void ldm_x2(uint32_t* r, uint32_t addr) {
    asm volatile(
        "ldmatrix.sync.aligned.m8n8.x2.shared.b16 {%0,%1}, [%2];"
        : "=r"(r[0]), "=r"(r[1]) : "r"(addr));
}
__device__ __forceinline__ void ldm_x2t(uint32_t* r, uint32_t addr) {
    asm volatile(
        "ldmatrix.sync.aligned.m8n8.x2.trans.shared.b16 {%0,%1}, [%2];"
        : "=r"(r[0]), "=r"(r[1]) : "r"(addr));
}

__device__ __forceinline__ void cpasync16(uint32_t dst, const void* src) {
    asm volatile("cp.async.cg.shared.global [%0], [%1], 16;" :: "r"(dst), "l"(src));
}
__device__ __forceinline__ void cp_commit() {
    asm volatile("cp.async.commit_group;" ::: "memory");
}
template<int N> __device__ __forceinline__ void cp_wait() {
    asm volatile("cp.async.wait_group %0;" :: "n"(N) : "memory");
}

// ---------------------------------------------------------------------------
// Kernel: elementwise split fp32 -> bf16 hi/lo
// ---------------------------------------------------------------------------
__global__ __launch_bounds__(256) void split_kernel(
    const float* __restrict__ in, __nv_bfloat16* __restrict__ h,
    __nv_bfloat16* __restrict__ l, int n)
{
    int i4 = (blockIdx.x * 256 + threadIdx.x) * 4;
    if (i4 >= n) return;
    float4 v = *(const float4*)(in + i4);
    uint32_t h0, l0, h1, l1;
    bsplit2(v.x, v.y, h0, l0);
    bsplit2(v.z, v.w, h1, l1);
    *(uint2*)((char*)h + (size_t)i4 * 2) = make_uint2(h0, h1);
    *(uint2*)((char*)l + (size_t)i4 * 2) = make_uint2(l0, l1);
}

// ---------------------------------------------------------------------------
// bf16-split GEMM: C[m,n] = sum_k A[m,k]*B[n,k] (+bias)
// BM=128, BN=128, BK=16, 128 threads (4 warps 2x2, warp tile 64x64).
// 3-stage cp.async, ldmatrix frags, 1 sync/iter, 2 CTAs/SM.
// mma:ldmatrix ratio = 96:16 per warp-iter (1.5x R12) -> tensor-dominant.
// Rows in smem: 16 bf16 (32B) + 16B pad = 48B stride (ldmatrix conflict-free).
// Stage: Ah@0 (6144) | Al@6144 | Bh@12288 (6144) | Bl@18432.  24576B/stage.
// ---------------------------------------------------------------------------
#define G_STAGE_BYTES 24576
#define G_SMEM_BYTES (3 * G_STAGE_BYTES)   // 73728

__global__ __launch_bounds__(128, 2) void gemm_bf16x3(
    const __nv_bfloat16* __restrict__ Ah, const __nv_bfloat16* __restrict__ Al,
    const __nv_bfloat16* __restrict__ Bh, const __nv_bfloat16* __restrict__ Bl,
    const float* __restrict__ bias, float* __restrict__ Cf,
    __nv_bfloat16* __restrict__ Ch, __nv_bfloat16* __restrict__ Cl,
    int M, int N, int K, int qscaleCols)
{
    extern __shared__ char smem[];
    const uint32_t sbase = smem_u32(smem);
    const int tid  = threadIdx.x;
    const int lane = tid & 31;
    const int warp = tid >> 5;
    const int g    = lane >> 2;
    const int q4   = lane & 3;
    const int wm   = warp >> 1;       // 0..1 (64 rows each)
    const int wn   = warp & 1;        // 0..1 (64 cols each)
    const int mBase = blockIdx.y * 128;
    const int nBase = blockIdx.x * 128;

    float acc[4][8][4];
#pragma unroll
    for (int i = 0; i < 4; ++i)
#pragma unroll
        for (int j = 0; j < 8; ++j)
#pragma unroll
            for (int c = 0; c < 4; ++c) acc[i][j][c] = 0.f;

    const int lj = lane >> 3, l7 = lane & 7;
    const uint32_t aRowBase = (uint32_t)(wm * 64 + (lj & 1) * 8 + l7) * 48
                              + (uint32_t)(lj >> 1) * 16;
    const uint32_t bRowBase = (uint32_t)(wn * 64 + (lj >> 1) * 8 + l7) * 48
                              + (uint32_t)(lj & 1) * 16;

    const int NT = K / 16;            // 64

    // gmem base pointers: each thread owns one row of A and one row of B
    const char* ApH = (const char*)(Ah + (size_t)(mBase + tid) * K);
    const char* ApL = (const char*)(Al + (size_t)(mBase + tid) * K);
    const char* BpH = (const char*)(Bh + (size_t)(nBase + tid) * K);
    const char* BpL = (const char*)(Bl + (size_t)(nBase + tid) * K);

#define G_ISSUE(ITER) do {                                                      \
    int s_ = (ITER) % 3;                                                        \
    int kb_ = (ITER) * 32;  /* byte offset along K */                           \
    uint32_t stb_ = sbase + s_ * G_STAGE_BYTES;                                 \
    _Pragma("unroll")                                                           \
    for (int j_ = 0; j_ < 2; ++j_) {                                            \
        cpasync16(stb_ + tid * 48 + j_ * 16, ApH + kb_ + j_ * 16);              \
        cpasync16(stb_ + 6144 + tid * 48 + j_ * 16, ApL + kb_ + j_ * 16);       \
        cpasync16(stb_ + 12288 + tid * 48 + j_ * 16, BpH + kb_ + j_ * 16);      \
        cpasync16(stb_ + 18432 + tid * 48 + j_ * 16, BpL + kb_ + j_ * 16);      \
    }                                                                           \
} while (0)

    G_ISSUE(0); cp_commit();
    G_ISSUE(1); cp_commit();

    for (int it = 0; it < NT; ++it) {
        if (it + 1 < NT) cp_wait<1>(); else cp_wait<0>();
        __syncthreads();
        if (it + 2 < NT) { G_ISSUE(it + 2); cp_commit(); }

        const uint32_t stb = sbase + (it % 3) * G_STAGE_BYTES;

        // A fragments: 64 rows x k16, hi and lo
        uint32_t ah[4][4], al[4][4];
#pragma unroll
        for (int mf = 0; mf < 4; ++mf) {
            ldm_x4(ah[mf], stb + aRowBase + mf * (16 * 48));
            ldm_x4(al[mf], stb + 6144 + aRowBase + mf * (16 * 48));
        }

        // B in two 32-col halves to cap live registers
#pragma unroll
        for (int half = 0; half < 2; ++half) {
            uint32_t bh[4][2], bl[4][2];
#pragma unroll
            for (int np = 0; np < 2; ++np) {
                uint32_t r[4];
                ldm_x4(r, stb + 12288 + bRowBase + (half * 2 + np) * (16 * 48));
                bh[np * 2][0] = r[0]; bh[np * 2][1] = r[1];
                bh[np * 2 + 1][0] = r[2]; bh[np * 2 + 1][1] = r[3];
                ldm_x4(r, stb + 18432 + bRowBase + (half * 2 + np) * (16 * 48));
                bl[np * 2][0] = r[0]; bl[np * 2][1] = r[1];
                bl[np * 2 + 1][0] = r[2]; bl[np * 2 + 1][1] = r[3];
            }
            // de-chained 3-term sweeps (acc reuse distance = 16 mmas)
#pragma unroll
            for (int mf = 0; mf < 4; ++mf)
#pragma unroll
                for (int nf = 0; nf < 4; ++nf)
                    mma_bf16(acc[mf][half * 4 + nf], ah[mf], bh[nf][0], bh[nf][1]);
#pragma unroll
            for (int mf = 0; mf < 4; ++mf)
#pragma unroll
                for (int nf = 0; nf < 4; ++nf)
                    mma_bf16(acc[mf][half * 4 + nf], ah[mf], bl[nf][0], bl[nf][1]);
#pragma unroll
            for (int mf = 0; mf < 4; ++mf)
#pragma unroll
                for (int nf = 0; nf < 4; ++nf)
                    mma_bf16(acc[mf][half * 4 + nf], al[mf], bh[nf][0], bh[nf][1]);
        }
    }
#undef G_ISSUE

    // Epilogue
    const int Np = N >> 1;
#pragma unroll
    for (int mf = 0; mf < 4; ++mf) {
        int r0 = mBase + wm * 64 + mf * 16 + g;
        int r1 = r0 + 8;
#pragma unroll
        for (int nf = 0; nf < 8; ++nf) {
            int col = nBase + wn * 64 + nf * 8 + 2 * q4;
            if (Cf) {
                float bx = bias ? bias[col] : 0.f;
                float by = bias ? bias[col + 1] : 0.f;
                *(float2*)(Cf + (size_t)r0 * N + col) =
                    make_float2(acc[mf][nf][0] + bx, acc[mf][nf][1] + by);
                *(float2*)(Cf + (size_t)r1 * N + col) =
                    make_float2(acc[mf][nf][2] + bx, acc[mf][nf][3] + by);
            } else {
                float sc = (col < qscaleCols) ? 0.125f : 1.f;
                uint32_t hi, lo;
                bsplit2(acc[mf][nf][0] * sc, acc[mf][nf][1] * sc, hi, lo);
                ((uint32_t*)Ch)[(size_t)r0 * Np + (col >> 1)] = hi;
                ((uint32_t*)Cl)[(size_t)r0 * Np + (col >> 1)] = lo;
                bsplit2(acc[mf][nf][2] * sc, acc[mf][nf][3] * sc, hi, lo);
                ((uint32_t*)Ch)[(size_t)r1 * Np + (col >> 1)] = hi;
                ((uint32_t*)Cl)[(size_t)r1 * Np + (col >> 1)] = lo;
            }
        }
    }
}

// ---------------------------------------------------------------------------
// Flash attention, bf16-split mma (m16n8k16), 2-stage cp.async KV pipeline.
// grid (S/64, B*H), 128 threads (4 warps x 16 q rows). Q pre-scaled by 0.125.
// qt DESCENDING. P stays in registers. K: ldmatrix.x2; V: ldmatrix.x2.trans.
// ---------------------------------------------------------------------------
#define A_QL 2304
#define A_ST 4608
#define A_STAGE_U32 9216
#define ATT_SMEM_BYTES ((A_ST + 2 * A_STAGE_U32) * 4)   // 92160

__global__ __launch_bounds__(128) void attn_bf16(
    const __nv_bfloat16* __restrict__ QKVh, const __nv_bfloat16* __restrict__ QKVl,
    __nv_bfloat16* __restrict__ Oh, __nv_bfloat16* __restrict__ Ol)
{
    extern __shared__ uint32_t sm4[];
    const uint32_t sbase = smem_u32(sm4);
    const int qt  = gridDim.x - 1 - blockIdx.x;   // heavy tiles first
    const int bh  = blockIdx.y;
    const int h   = bh & 15;
    const int b   = bh >> 4;
    const int tid = threadIdx.x;
    const int w    = tid >> 5;
    const int lane = tid & 31;
    const int g    = lane >> 2;
    const int q4   = lane & 3;
    const int qBase = qt * 64;

#define KV_ISSUE(KT) do {                                                       \
    int s_ = (KT) & 1;                                                          \
    uint32_t stb_ = sbase + (A_ST + s_ * A_STAGE_U32) * 4;                      \
    _Pragma("unroll")                                                           \
    for (int j_ = 0; j_ < 4; ++j_) {                                            \
        int id_ = tid + j_ * 128;                                               \
        int row_ = id_ >> 3, ch_ = id_ & 7;                                     \
        size_t ks_ = (size_t)(((KT) * 64 + row_) * BATCH + b) * (3 * DMODEL)    \
                     + DMODEL + h * DKH;                                        \
        size_t vs_ = ks_ + DMODEL;                                              \
        cpasync16(stb_ + row_ * 144 + ch_ * 16, (const char*)(QKVh + ks_) + ch_ * 16); \
        cpasync16(stb_ + 9216 + row_ * 144 + ch_ * 16, (const char*)(QKVl + ks_) + ch_ * 16); \
        cpasync16(stb_ + 18432 + row_ * 144 + ch_ * 16, (const char*)(QKVh + vs_) + ch_ * 16); \
        cpasync16(stb_ + 27648 + row_ * 144 + ch_ * 16, (const char*)(QKVl + vs_) + ch_ * 16); \
    }                                                                           \
} while (0)

    KV_ISSUE(0); cp_commit();

    // Load Q tile (split, already scaled): 64 rows x 128B per array
#pragma unroll
    for (int j = 0; j < 4; ++j) {
        int id = tid + j * 128;
        int row = id >> 3, ch = id & 7;
        size_t src = (size_t)((qBase + row) * BATCH + b) * (3 * DMODEL) + h * DKH;
        uint4 vh = *(const uint4*)((const char*)(QKVh + src) + ch * 16);
        uint4 vl = *(const uint4*)((const char*)(QKVl + src) + ch * 16);
        *(uint4*)((char*)sm4 + row * 144 + ch * 16) = vh;
        *(uint4*)((char*)sm4 + A_QL * 4 + row * 144 + ch * 16) = vl;
    }
    __syncthreads();

    // Q fragments
    uint32_t qh[4][4], ql[4][4];
    {
        int r0 = (w * 16 + g) * 36;
        int r1 = r0 + 288;
#pragma unroll
        for (int kc = 0; kc < 4; ++kc) {
            qh[kc][0] = sm4[r0 + kc * 8 + q4];
            qh[kc][1] = sm4[r1 + kc * 8 + q4];
            qh[kc][2] = sm4[r0 + kc * 8 + 4 + q4];
            qh[kc][3] = sm4[r1 + kc * 8 + 4 + q4];
            ql[kc][0] = sm4[A_QL + r0 + kc * 8 + q4];
            ql[kc][1] = sm4[A_QL + r1 + kc * 8 + q4];
            ql[kc][2] = sm4[A_QL + r0 + kc * 8 + 4 + q4];
            ql[kc][3] = sm4[A_QL + r1 + kc * 8 + 4 + q4];
        }
    }

    float ofr[8][4];
#pragma unroll
    for (int nt = 0; nt < 8; ++nt)
#pragma unroll
        for (int c = 0; c < 4; ++c) ofr[nt][c] = 0.f;

    float m0 = -INFINITY, m1 = -INFINITY, l0 = 0.f, l1 = 0.f;
    const int qrow0 = qBase + w * 16 + g;
    const int qrow1 = qrow0 + 8;

    // ldmatrix per-lane address terms
    const int l7  = lane & 7;
    const int l15 = lane & 15;
    const uint32_t kLane = (uint32_t)l7 * 144 + (uint32_t)((lane >> 3) & 1) * 16;
    const uint32_t vLane = (uint32_t)l15 * 144;

    for (int kt = 0; kt <= qt; ++kt) {
        cp_wait<0>();
        __syncthreads();
        if (kt < qt) { KV_ISSUE(kt + 1); cp_commit(); }

        const uint32_t stb = sbase + (A_ST + (kt & 1) * A_STAGE_U32) * 4;
        const uint32_t stbKH = stb + kLane;
        const uint32_t stbKL = stbKH + 9216;
        const uint32_t stbVH = stb + 18432 + vLane;
        const uint32_t stbVL = stbVH + 9216;

        // S = Q K^T (3 de-chained sweeps per kc)
        float sfr[8][4];
#pragma unroll
        for (int nt = 0; nt < 8; ++nt)
#pragma unroll
            for (int c = 0; c < 4; ++c) sfr[nt][c] = 0.f;

#pragma unroll
        for (int kc = 0; kc < 4; ++kc) {
            uint32_t kh2[8][2], kl2[8][2];
#pragma unroll
            for (int nt = 0; nt < 8; ++nt) {
                ldm_x2(kh2[nt], stbKH + nt * (8 * 144) + kc * 32);
                ldm_x2(kl2[nt], stbKL + nt * (8 * 144) + kc * 32);
            }
#pragma unroll
            for (int nt = 0; nt < 8; ++nt)
                mma_bf16(sfr[nt], qh[kc], kh2[nt][0], kh2[nt][1]);
#pragma unroll
            for (int nt = 0; nt < 8; ++nt)
                mma_bf16(sfr[nt], qh[kc], kl2[nt][0], kl2[nt][1]);
#pragma unroll
            for (int nt = 0; nt < 8; ++nt)
                mma_bf16(sfr[nt], ql[kc], kh2[nt][0], kh2[nt][1]);
        }

        // Causal mask (diagonal tile only)
        if (kt == qt) {
#pragma unroll
            for (int nt = 0; nt < 8; ++nt) {
                int key = kt * 64 + nt * 8 + 2 * q4;
                if (key     > qrow0) sfr[nt][0] = -INFINITY;
                if (key + 1 > qrow0) sfr[nt][1] = -INFINITY;
                if (key     > qrow1) sfr[nt][2] = -INFINITY;
                if (key + 1 > qrow1) sfr[nt][3] = -INFINITY;
            }
        }

        // Online softmax
        float mx0 = -INFINITY, mx1 = -INFINITY;
#pragma unroll
        for (int nt = 0; nt < 8; ++nt) {
            mx0 = fmaxf(mx0, fmaxf(sfr[nt][0], sfr[nt][1]));
            mx1 = fmaxf(mx1, fmaxf(sfr[nt][2], sfr[nt][3]));
        }
        mx0 = fmaxf(mx0, __shfl_xor_sync(0xffffffffu, mx0, 1));
        mx0 = fmaxf(mx0, __shfl_xor_sync(0xffffffffu, mx0, 2));
        mx1 = fmaxf(mx1, __shfl_xor_sync(0xffffffffu, mx1, 1));
        mx1 = fmaxf(mx1, __shfl_xor_sync(0xffffffffu, mx1, 2));

        float mn0 = fmaxf(m0, mx0), mn1 = fmaxf(m1, mx1);
        float cr0 = __expf(m0 - mn0), cr1 = __expf(m1 - mn1);
        l0 *= cr0; l1 *= cr1;
        m0 = mn0;  m1 = mn1;

        // exp -> P fragments directly in registers
        uint32_t aph[8][2], apl[8][2];
        float ps0 = 0.f, ps1 = 0.f;
#pragma unroll
        for (int nt = 0; nt < 8; ++nt) {
            ofr[nt][0] *= cr0; ofr[nt][1] *= cr0;
            ofr[nt][2] *= cr1; ofr[nt][3] *= cr1;
            float p0 = __expf(sfr[nt][0] - m0);
            float p1 = __expf(sfr[nt][1] - m0);
            float p2 = __expf(sfr[nt][2] - m1);
            float p3 = __expf(sfr[nt][3] - m1);
            ps0 += p0 + p1; ps1 += p2 + p3;
            bsplit2(p0, p1, aph[nt][0], apl[nt][0]);
            bsplit2(p2, p3, aph[nt][1], apl[nt][1]);
        }
        ps0 += __shfl_xor_sync(0xffffffffu, ps0, 1);
        ps0 += __shfl_xor_sync(0xffffffffu, ps0, 2);
        ps1 += __shfl_xor_sync(0xffffffffu, ps1, 1);
        ps1 += __shfl_xor_sync(0xffffffffu, ps1, 2);
        l0 += ps0; l1 += ps1;

        // O += P V  (V fragments via ldmatrix.trans on K-major V rows)
#pragma unroll
        for (int kc = 0; kc < 4; ++kc) {
            uint32_t pah[4] = {aph[2 * kc][0], aph[2 * kc][1],
                               aph[2 * kc + 1][0], aph[2 * kc + 1][1]};
            uint32_t pal[4] = {apl[2 * kc][0], apl[2 * kc][1],
                               apl[2 * kc + 1][0], apl[2 * kc + 1][1]};
            uint32_t vh2[8][2], vl2[8][2];
#pragma unroll
            for (int nt = 0; nt < 8; ++nt) {
                ldm_x2t(vh2[nt], stbVH + kc * (16 * 144) + nt * 16);
                ldm_x2t(vl2[nt], stbVL + kc * (16 * 144) + nt * 16);
            }
#pragma unroll
            for (int nt = 0; nt < 8; ++nt)
                mma_bf16(ofr[nt], pah, vh2[nt][0], vh2[nt][1]);
#pragma unroll
            for (int nt = 0; nt < 8; ++nt)
                mma_bf16(ofr[nt], pah, vl2[nt][0], vl2[nt][1]);
#pragma unroll
            for (int nt = 0; nt < 8; ++nt)
                mma_bf16(ofr[nt], pal, vh2[nt][0], vh2[nt][1]);
        }
    }
#undef KV_ISSUE

    // Epilogue: normalize, split-write attention output
    float inv0 = 1.f / l0, inv1 = 1.f / l1;
    size_t row0 = (size_t)(qrow0 * BATCH + b) * (DMODEL / 2);
    size_t row1 = (size_t)(qrow1 * BATCH + b) * (DMODEL / 2);
#pragma unroll
    for (int nt = 0; nt < 8; ++nt) {
        int pcol = h * 32 + nt * 4 + q4;
        uint32_t hi, lo;
        bsplit2(ofr[nt][0] * inv0, ofr[nt][1] * inv0, hi, lo);
        ((uint32_t*)Oh)[row0 + pcol] = hi;
        ((uint32_t*)Ol)[row0 + pcol] = lo;
        bsplit2(ofr[nt][2] * inv1, ofr[nt][3] * inv1, hi, lo);
        ((uint32_t*)Oh)[row1 + pcol] = hi;
        ((uint32_t*)Ol)[row1 + pcol] = lo;
    }
}

// ---------------------------------------------------------------------------
extern "C" void kernel_launch(void* const* d_in, const int* in_sizes, int n_in,
                              void* d_out, int out_size)
{
    const float* x     = (const float*)d_in[0];   // [S,B,D]
    const float* w_qkv = (const float*)d_in[1];   // [3D,D]
    const float* w_out = (const float*)d_in[2];   // [D,D]
    const float* b_out = (const float*)d_in[3];   // [D]
    float* out = (float*)d_out;

    __nv_bfloat16 *xh, *xl, *wqh, *wql, *woh, *wol, *qkvh, *qkvl, *ah, *al;
    cudaGetSymbolAddress((void**)&xh,   g_xh);
    cudaGetSymbolAddress((void**)&xl,   g_xl);
    cudaGetSymbolAddress((void**)&wqh,  g_wqh);
    cudaGetSymbolAddress((void**)&wql,  g_wql);
    cudaGetSymbolAddress((void**)&woh,  g_woh);
    cudaGetSymbolAddress((void**)&wol,  g_wol);
    cudaGetSymbolAddress((void**)&qkvh, g_qkvh);
    cudaGetSymbolAddress((void**)&qkvl, g_qkvl);
    cudaGetSymbolAddress((void**)&ah,   g_ah);
    cudaGetSymbolAddress((void**)&al,   g_al);

    cudaFuncSetAttribute(gemm_bf16x3,
                         cudaFuncAttributeMaxDynamicSharedMemorySize, G_SMEM_BYTES);
    cudaFuncSetAttribute(attn_bf16,
                         cudaFuncAttributeMaxDynamicSharedMemorySize, ATT_SMEM_BYTES);

    // 0) Split inputs to bf16 hi/lo
    {
        int n1 = MROWS * DMODEL;        // x
        int n2 = 3 * DMODEL * DMODEL;   // w_qkv
        int n3 = DMODEL * DMODEL;       // w_out
        split_kernel<<<(n1 / 4 + 255) / 256, 256>>>(x, xh, xl, n1);
        split_kernel<<<(n2 / 4 + 255) / 256, 256>>>(w_qkv, wqh, wql, n2);
        split_kernel<<<(n3 / 4 + 255) / 256, 256>>>(w_out, woh, wol, n3);
    }

    // 1) QKV projection -> split qkv (Q cols scaled by 0.125)
    gemm_bf16x3<<<dim3(3 * DMODEL / 128, MROWS / 128), 128, G_SMEM_BYTES>>>(
        xh, xl, wqh, wql, nullptr, nullptr, qkvh, qkvl,
        MROWS, 3 * DMODEL, DMODEL, DMODEL);

    // 2) Causal flash attention -> split attention output
    attn_bf16<<<dim3(S_LEN / 64, BATCH * NH), 128, ATT_SMEM_BYTES>>>(
        qkvh, qkvl, ah, al);

    // 3) Output projection + bias -> fp32 out
    gemm_bf16x3<<<dim3(DMODEL / 128, MROWS / 128), 128, G_SMEM_BYTES>>>(
        ah, al, woh, wol, b_out, out, nullptr, nullptr,
        MROWS, DMODEL, DMODEL, 0);
}

// round 16
// speedup vs baseline: 1.5805x; 1.1369x over previous
#include <cuda_runtime.h>
#include <cuda_bf16.h>
#include <math.h>
#include <stdint.h>

// Problem constants
#define S_LEN 2048
#define BATCH 2
#define DMODEL 1024
#define NH 16
#define DKH 64
#define MROWS (S_LEN * BATCH)   // 4096

// ---------------------------------------------------------------------------
// Scratch (allocation-free rule: __device__ globals). All split-bf16 pairs.
// ---------------------------------------------------------------------------
__device__ __nv_bfloat16 g_xh[(size_t)MROWS * DMODEL];
__device__ __nv_bfloat16 g_xl[(size_t)MROWS * DMODEL];
__device__ __nv_bfloat16 g_wqh[(size_t)3 * DMODEL * DMODEL];
__device__ __nv_bfloat16 g_wql[(size_t)3 * DMODEL * DMODEL];
__device__ __nv_bfloat16 g_woh[(size_t)DMODEL * DMODEL];
__device__ __nv_bfloat16 g_wol[(size_t)DMODEL * DMODEL];
__device__ __nv_bfloat16 g_qkvh[(size_t)MROWS * 3 * DMODEL];
__device__ __nv_bfloat16 g_qkvl[(size_t)MROWS * 3 * DMODEL];
__device__ __nv_bfloat16 g_ah[(size_t)MROWS * DMODEL];
__device__ __nv_bfloat16 g_al[(size_t)MROWS * DMODEL];

// ---------------------------------------------------------------------------
// Helpers
// ---------------------------------------------------------------------------
__device__ __forceinline__ uint32_t smem_u32(const void* p) {
    uint32_t a;
    asm("{ .reg .u64 t; cvta.to.shared.u64 t, %1; cvt.u32.u64 %0, t; }"
        : "=r"(a) : "l"(p));
    return a;
}

// split (x,y) -> packed bf16x2 hi + packed bf16x2 lo
__device__ __forceinline__ void bsplit2(float x, float y, uint32_t& hi, uint32_t& lo) {
    __nv_bfloat16 hx = __float2bfloat16(x);
    __nv_bfloat16 hy = __float2bfloat16(y);
    __nv_bfloat16 lx = __float2bfloat16(x - __bfloat162float(hx));
    __nv_bfloat16 ly = __float2bfloat16(y - __bfloat162float(hy));
    hi = (uint32_t)__bfloat16_as_ushort(hx) | ((uint32_t)__bfloat16_as_ushort(hy) << 16);
    lo = (uint32_t)__bfloat16_as_ushort(lx) | ((uint32_t)__bfloat16_as_ushort(ly) << 16);
}

// m16n8k16 bf16 mma, D (f32) += A * B
__device__ __forceinline__ void mma_bf16(float* d, const uint32_t* a,
                                         uint32_t b0, uint32_t b1) {
    asm volatile(
        "mma.sync.aligned.m16n8k16.row.col.f32.bf16.bf16.f32 "
        "{%0,%1,%2,%3},{%4,%5,%6,%7},{%8,%9},{%0,%1,%2,%3};"
        : "+f"(d[0]), "+f"(d[1]), "+f"(d[2]), "+f"(d[3])
        : "r"(a[0]), "r"(a[1]), "r"(a[2]), "r"(a[3]), "r"(b0), "r"(b1));
}

__device__ __forceinline__ void ldm_x4(uint32_t* r, uint32_t addr) {
    asm volatile(
        "ldmatrix.sync.aligned.m8n8.x4.shared.b16 {%0,%1,%2,%3}, [%4];"
        : "=r"(r[0]), "=r"(r[1]), "=r"(r[2]), "=r"(r[3]) : "r"(addr));
}
__device__ __forceinline__ void ldm_x2(uint32_t* r, uint32_t addr) {
    asm volatile(
        "ldmatrix.sync.aligned.m8n8.x2.shared.b16 {%0,%1}, [%2];"
        : "=r"(r[0]), "=r"(r[1]) : "r"(addr));
}
__device__ __forceinline__ void ldm_x2t(uint32_t* r, uint32_t addr) {
    asm volatile(
        "ldmatrix.sync.aligned.m8n8.x2.trans.shared.b16 {%0,%1}, [%2];"
        : "=r"(r[0]), "=r"(r[1]) : "r"(addr));
}

__device__ __forceinline__ void cpasync16(uint32_t dst, const void* src) {
    asm volatile("cp.async.cg.shared.global [%0], [%1], 16;" :: "r"(dst), "l"(src));
}
__device__ __forceinline__ void cp_commit() {
    asm volatile("cp.async.commit_group;" ::: "memory");
}
template<int N> __device__ __forceinline__ void cp_wait() {
    asm volatile("cp.async.wait_group %0;" :: "n"(N) : "memory");
}

// ---------------------------------------------------------------------------
// Kernel: elementwise split fp32 -> bf16 hi/lo
// ---------------------------------------------------------------------------
__global__ __launch_bounds__(256) void split_kernel(
    const float* __restrict__ in, __nv_bfloat16* __restrict__ h,
    __nv_bfloat16* __restrict__ l, int n)
{
    int i4 = (blockIdx.x * 256 + threadIdx.x) * 4;
    if (i4 >= n) return;
    float4 v = *(const float4*)(in + i4);
    uint32_t h0, l0, h1, l1;
    bsplit2(v.x, v.y, h0, l0);
    bsplit2(v.z, v.w, h1, l1);
    *(uint2*)((char*)h + (size_t)i4 * 2) = make_uint2(h0, h1);
    *(uint2*)((char*)l + (size_t)i4 * 2) = make_uint2(l0, l1);
}

// ---------------------------------------------------------------------------
// bf16-split GEMM: C[m,n] = sum_k A[m,k]*B[n,k] (+bias)
// BM=128, BN=64, BK=32, 128 threads (4 warps, 2x2, warp tile 64x32).
// 2-stage cp.async (61.4KB smem), ldmatrix frags, 1 sync/iter.
// __launch_bounds__(128,3): 3 CTAs/SM, 12 warps/SM, 3 warps/SMSP — third
// independent stream to fill ldmatrix->HMMA and barrier bubbles.
// Rows in smem: 32 bf16 (64B) + 16B pad = 80B stride (ldmatrix conflict-free).
// Stage: Ah@0 (10240) | Al@10240 | Bh@20480 (5120) | Bl@25600.  30720B/stage.
// ---------------------------------------------------------------------------
#define G_STAGE_BYTES 30720
#define G_SMEM_BYTES (2 * G_STAGE_BYTES)   // 61440

__global__ __launch_bounds__(128, 3) void gemm_bf16x3(
    const __nv_bfloat16* __restrict__ Ah, const __nv_bfloat16* __restrict__ Al,
    const __nv_bfloat16* __restrict__ Bh, const __nv_bfloat16* __restrict__ Bl,
    const float* __restrict__ bias, float* __restrict__ Cf,
    __nv_bfloat16* __restrict__ Ch, __nv_bfloat16* __restrict__ Cl,
    int M, int N, int K, int qscaleCols)
{
    extern __shared__ char smem[];
    const uint32_t sbase = smem_u32(smem);
    const int tid  = threadIdx.x;
    const int lane = tid & 31;
    const int warp = tid >> 5;
    const int g    = lane >> 2;
    const int q4   = lane & 3;
    const int wm   = warp >> 1;       // 0..1 (64 rows each)
    const int wn   = warp & 1;        // 0..1 (32 cols each)
    const int mBase = blockIdx.y * 128;
    const int nBase = blockIdx.x * 64;

    float acc[4][4][4];
#pragma unroll
    for (int i = 0; i < 4; ++i)
#pragma unroll
        for (int j = 0; j < 4; ++j)
#pragma unroll
            for (int c = 0; c < 4; ++c) acc[i][j][c] = 0.f;

    const int lj = lane >> 3, l7 = lane & 7;
    const uint32_t aRowBase = (uint32_t)(wm * 64 + (lj & 1) * 8 + l7) * 80
                              + (uint32_t)(lj >> 1) * 16;
    const uint32_t bRowBase = (uint32_t)(wn * 32 + (lj >> 1) * 8 + l7) * 80
                              + (uint32_t)(lj & 1) * 16;

    const int NT = K / 32;            // 32

#define G_ISSUE(ITER) do {                                                      \
    int s_ = (ITER) & 1;                                                        \
    int k0_ = (ITER) * 32;                                                      \
    uint32_t stb_ = sbase + s_ * G_STAGE_BYTES;                                 \
    _Pragma("unroll")                                                           \
    for (int j_ = 0; j_ < 4; ++j_) {  /* Ah then Al */                          \
        int cid_ = tid + j_ * 128;                                              \
        int row_ = cid_ >> 2, ch_ = cid_ & 3;                                   \
        cpasync16(stb_ + row_ * 80 + ch_ * 16,                                  \
                  (const char*)(Ah + (size_t)(mBase + row_) * K + k0_) + ch_ * 16); \
        cpasync16(stb_ + 10240 + row_ * 80 + ch_ * 16,                          \
                  (const char*)(Al + (size_t)(mBase + row_) * K + k0_) + ch_ * 16); \
    }                                                                           \
    _Pragma("unroll")                                                           \
    for (int j_ = 0; j_ < 2; ++j_) {  /* Bh then Bl */                          \
        int cid_ = tid + j_ * 128;                                              \
        int row_ = cid_ >> 2, ch_ = cid_ & 3;                                   \
        cpasync16(stb_ + 20480 + row_ * 80 + ch_ * 16,                          \
                  (const char*)(Bh + (size_t)(nBase + row_) * K + k0_) + ch_ * 16); \
        cpasync16(stb_ + 25600 + row_ * 80 + ch_ * 16,                          \
                  (const char*)(Bl + (size_t)(nBase + row_) * K + k0_) + ch_ * 16); \
    }                                                                           \
} while (0)

    G_ISSUE(0); cp_commit();

    for (int it = 0; it < NT; ++it) {
        cp_wait<0>();                 // stage `it` landed
        __syncthreads();              // all warps done with the other stage
        if (it + 1 < NT) { G_ISSUE(it + 1); cp_commit(); }

        const uint32_t stb = sbase + (it & 1) * G_STAGE_BYTES;

#pragma unroll
        for (int ks = 0; ks < 2; ++ks) {
            const uint32_t kk = ks * 32;
            uint32_t ah[4][4], al[4][4];
#pragma unroll
            for (int mf = 0; mf < 4; ++mf) {
                ldm_x4(ah[mf], stb + aRowBase + mf * (16 * 80) + kk);
                ldm_x4(al[mf], stb + 10240 + aRowBase + mf * (16 * 80) + kk);
            }
            uint32_t bh[4][2], bl[4][2];
#pragma unroll
            for (int np = 0; np < 2; ++np) {
                uint32_t r[4];
                ldm_x4(r, stb + 20480 + bRowBase + np * (16 * 80) + kk);
                bh[np * 2][0] = r[0]; bh[np * 2][1] = r[1];
                bh[np * 2 + 1][0] = r[2]; bh[np * 2 + 1][1] = r[3];
                ldm_x4(r, stb + 25600 + bRowBase + np * (16 * 80) + kk);
                bl[np * 2][0] = r[0]; bl[np * 2][1] = r[1];
                bl[np * 2 + 1][0] = r[2]; bl[np * 2 + 1][1] = r[3];
            }
            // de-chained 3-term sweeps (acc reuse distance = 16 mmas)
#pragma unroll
            for (int mf = 0; mf < 4; ++mf)
#pragma unroll
                for (int nf = 0; nf < 4; ++nf)
                    mma_bf16(acc[mf][nf], ah[mf], bh[nf][0], bh[nf][1]);
#pragma unroll
            for (int mf = 0; mf < 4; ++mf)
#pragma unroll
                for (int nf = 0; nf < 4; ++nf)
                    mma_bf16(acc[mf][nf], ah[mf], bl[nf][0], bl[nf][1]);
#pragma unroll
            for (int mf = 0; mf < 4; ++mf)
#pragma unroll
                for (int nf = 0; nf < 4; ++nf)
                    mma_bf16(acc[mf][nf], al[mf], bh[nf][0], bh[nf][1]);
        }
    }
#undef G_ISSUE

    // Epilogue
    const int Np = N >> 1;
#pragma unroll
    for (int mf = 0; mf < 4; ++mf) {
        int r0 = mBase + wm * 64 + mf * 16 + g;
        int r1 = r0 + 8;
#pragma unroll
        for (int nf = 0; nf < 4; ++nf) {
            int col = nBase + wn * 32 + nf * 8 + 2 * q4;
            if (Cf) {
                float bx = bias ? bias[col] : 0.f;
                float by = bias ? bias[col + 1] : 0.f;
                *(float2*)(Cf + (size_t)r0 * N + col) =
                    make_float2(acc[mf][nf][0] + bx, acc[mf][nf][1] + by);
                *(float2*)(Cf + (size_t)r1 * N + col) =
                    make_float2(acc[mf][nf][2] + bx, acc[mf][nf][3] + by);
            } else {
                float sc = (col < qscaleCols) ? 0.125f : 1.f;
                uint32_t hi, lo;
                bsplit2(acc[mf][nf][0] * sc, acc[mf][nf][1] * sc, hi, lo);
                ((uint32_t*)Ch)[(size_t)r0 * Np + (col >> 1)] = hi;
                ((uint32_t*)Cl)[(size_t)r0 * Np + (col >> 1)] = lo;
                bsplit2(acc[mf][nf][2] * sc, acc[mf][nf][3] * sc, hi, lo);
                ((uint32_t*)Ch)[(size_t)r1 * Np + (col >> 1)] = hi;
                ((uint32_t*)Cl)[(size_t)r1 * Np + (col >> 1)] = lo;
            }
        }
    }
}

// ---------------------------------------------------------------------------
// Flash attention, bf16-split mma (m16n8k16), 2-stage cp.async KV pipeline.
// grid (S/64, B*H), 128 threads (4 warps x 16 q rows). Q pre-scaled by 0.125.
// qt DESCENDING. P stays in registers. K: ldmatrix.x2; V: ldmatrix.x2.trans.
// (Unchanged from the 552us best — isolates the GEMM experiment.)
// ---------------------------------------------------------------------------
#define A_QL 2304
#define A_ST 4608
#define A_STAGE_U32 9216
#define ATT_SMEM_BYTES ((A_ST + 2 * A_STAGE_U32) * 4)   // 92160

__global__ __launch_bounds__(128) void attn_bf16(
    const __nv_bfloat16* __restrict__ QKVh, const __nv_bfloat16* __restrict__ QKVl,
    __nv_bfloat16* __restrict__ Oh, __nv_bfloat16* __restrict__ Ol)
{
    extern __shared__ uint32_t sm4[];
    const uint32_t sbase = smem_u32(sm4);
    const int qt  = gridDim.x - 1 - blockIdx.x;   // heavy tiles first
    const int bh  = blockIdx.y;
    const int h   = bh & 15;
    const int b   = bh >> 4;
    const int tid = threadIdx.x;
    const int w    = tid >> 5;
    const int lane = tid & 31;
    const int g    = lane >> 2;
    const int q4   = lane & 3;
    const int qBase = qt * 64;

#define KV_ISSUE(KT) do {                                                       \
    int s_ = (KT) & 1;                                                          \
    uint32_t stb_ = sbase + (A_ST + s_ * A_STAGE_U32) * 4;                      \
    _Pragma("unroll")                                                           \
    for (int j_ = 0; j_ < 4; ++j_) {                                            \
        int id_ = tid + j_ * 128;                                               \
        int row_ = id_ >> 3, ch_ = id_ & 7;                                     \
        size_t ks_ = (size_t)(((KT) * 64 + row_) * BATCH + b) * (3 * DMODEL)    \
                     + DMODEL + h * DKH;                                        \
        size_t vs_ = ks_ + DMODEL;                                              \
        cpasync16(stb_ + row_ * 144 + ch_ * 16, (const char*)(QKVh + ks_) + ch_ * 16); \
        cpasync16(stb_ + 9216 + row_ * 144 + ch_ * 16, (const char*)(QKVl + ks_) + ch_ * 16); \
        cpasync16(stb_ + 18432 + row_ * 144 + ch_ * 16, (const char*)(QKVh + vs_) + ch_ * 16); \
        cpasync16(stb_ + 27648 + row_ * 144 + ch_ * 16, (const char*)(QKVl + vs_) + ch_ * 16); \
    }                                                                           \
} while (0)

    KV_ISSUE(0); cp_commit();

    // Load Q tile (split, already scaled): 64 rows x 128B per array
#pragma unroll
    for (int j = 0; j < 4; ++j) {
        int id = tid + j * 128;
        int row = id >> 3, ch = id & 7;
        size_t src = (size_t)((qBase + row) * BATCH + b) * (3 * DMODEL) + h * DKH;
        uint4 vh = *(const uint4*)((const char*)(QKVh + src) + ch * 16);
        uint4 vl = *(const uint4*)((const char*)(QKVl + src) + ch * 16);
        *(uint4*)((char*)sm4 + row * 144 + ch * 16) = vh;
        *(uint4*)((char*)sm4 + A_QL * 4 + row * 144 + ch * 16) = vl;
    }
    __syncthreads();

    // Q fragments
    uint32_t qh[4][4], ql[4][4];
    {
        int r0 = (w * 16 + g) * 36;
        int r1 = r0 + 288;
#pragma unroll
        for (int kc = 0; kc < 4; ++kc) {
            qh[kc][0] = sm4[r0 + kc * 8 + q4];
            qh[kc][1] = sm4[r1 + kc * 8 + q4];
            qh[kc][2] = sm4[r0 + kc * 8 + 4 + q4];
            qh[kc][3] = sm4[r1 + kc * 8 + 4 + q4];
            ql[kc][0] = sm4[A_QL + r0 + kc * 8 + q4];
            ql[kc][1] = sm4[A_QL + r1 + kc * 8 + q4];
            ql[kc][2] = sm4[A_QL + r0 + kc * 8 + 4 + q4];
            ql[kc][3] = sm4[A_QL + r1 + kc * 8 + 4 + q4];
        }
    }

    float ofr[8][4];
#pragma unroll
    for (int nt = 0; nt < 8; ++nt)
#pragma unroll
        for (int c = 0; c < 4; ++c) ofr[nt][c] = 0.f;

    float m0 = -INFINITY, m1 = -INFINITY, l0 = 0.f, l1 = 0.f;
    const int qrow0 = qBase + w * 16 + g;
    const int qrow1 = qrow0 + 8;

    // ldmatrix per-lane address terms
    const int l7  = lane & 7;
    const int l15 = lane & 15;
    const uint32_t kLane = (uint32_t)l7 * 144 + (uint32_t)((lane >> 3) & 1) * 16;
    const uint32_t vLane = (uint32_t)l15 * 144;

    for (int kt = 0; kt <= qt; ++kt) {
        cp_wait<0>();
        __syncthreads();
        if (kt < qt) { KV_ISSUE(kt + 1); cp_commit(); }

        const uint32_t stb = sbase + (A_ST + (kt & 1) * A_STAGE_U32) * 4;
        const uint32_t stbKH = stb + kLane;
        const uint32_t stbKL = stbKH + 9216;
        const uint32_t stbVH = stb + 18432 + vLane;
        const uint32_t stbVL = stbVH + 9216;

        // S = Q K^T (3 de-chained sweeps per kc)
        float sfr[8][4];
#pragma unroll
        for (int nt = 0; nt < 8; ++nt)
#pragma unroll
            for (int c = 0; c < 4; ++c) sfr[nt][c] = 0.f;

#pragma unroll
        for (int kc = 0; kc < 4; ++kc) {
            uint32_t kh2[8][2], kl2[8][2];
#pragma unroll
            for (int nt = 0; nt < 8; ++nt) {
                ldm_x2(kh2[nt], stbKH + nt * (8 * 144) + kc * 32);
                ldm_x2(kl2[nt], stbKL + nt * (8 * 144) + kc * 32);
            }
#pragma unroll
            for (int nt = 0; nt < 8; ++nt)
                mma_bf16(sfr[nt], qh[kc], kh2[nt][0], kh2[nt][1]);
#pragma unroll
            for (int nt = 0; nt < 8; ++nt)
                mma_bf16(sfr[nt], qh[kc], kl2[nt][0], kl2[nt][1]);
#pragma unroll
            for (int nt = 0; nt < 8; ++nt)
                mma_bf16(sfr[nt], ql[kc], kh2[nt][0], kh2[nt][1]);
        }

        // Causal mask (diagonal tile only)
        if (kt == qt) {
#pragma unroll
            for (int nt = 0; nt < 8; ++nt) {
                int key = kt * 64 + nt * 8 + 2 * q4;
                if (key     > qrow0) sfr[nt][0] = -INFINITY;
                if (key + 1 > qrow0) sfr[nt][1] = -INFINITY;
                if (key     > qrow1) sfr[nt][2] = -INFINITY;
                if (key + 1 > qrow1) sfr[nt][3] = -INFINITY;
            }
        }

        // Online softmax
        float mx0 = -INFINITY, mx1 = -INFINITY;
#pragma unroll
        for (int nt = 0; nt < 8; ++nt) {
            mx0 = fmaxf(mx0, fmaxf(sfr[nt][0], sfr[nt][1]));
            mx1 = fmaxf(mx1, fmaxf(sfr[nt][2], sfr[nt][3]));
        }
        mx0 = fmaxf(mx0, __shfl_xor_sync(0xffffffffu, mx0, 1));
        mx0 = fmaxf(mx0, __shfl_xor_sync(0xffffffffu, mx0, 2));
        mx1 = fmaxf(mx1, __shfl_xor_sync(0xffffffffu, mx1, 1));
        mx1 = fmaxf(mx1, __shfl_xor_sync(0xffffffffu, mx1, 2));

        float mn0 = fmaxf(m0, mx0), mn1 = fmaxf(m1, mx1);
        float cr0 = __expf(m0 - mn0), cr1 = __expf(m1 - mn1);
        l0 *= cr0; l1 *= cr1;
        m0 = mn0;  m1 = mn1;

        // exp -> P fragments directly in registers
        uint32_t aph[8][2], apl[8][2];
        float ps0 = 0.f, ps1 = 0.f;
#pragma unroll
        for (int nt = 0; nt < 8; ++nt) {
            ofr[nt][0] *= cr0; ofr[nt][1] *= cr0;
            ofr[nt][2] *= cr1; ofr[nt][3] *= cr1;
            float p0 = __expf(sfr[nt][0] - m0);
            float p1 = __expf(sfr[nt][1] - m0);
            float p2 = __expf(sfr[nt][2] - m1);
            float p3 = __expf(sfr[nt][3] - m1);
            ps0 += p0 + p1; ps1 += p2 + p3;
            bsplit2(p0, p1, aph[nt][0], apl[nt][0]);
            bsplit2(p2, p3, aph[nt][1], apl[nt][1]);
        }
        ps0 += __shfl_xor_sync(0xffffffffu, ps0, 1);
        ps0 += __shfl_xor_sync(0xffffffffu, ps0, 2);
        ps1 += __shfl_xor_sync(0xffffffffu, ps1, 1);
        ps1 += __shfl_xor_sync(0xffffffffu, ps1, 2);
        l0 += ps0; l1 += ps1;

        // O += P V  (V fragments via ldmatrix.trans on K-major V rows)
#pragma unroll
        for (int kc = 0; kc < 4; ++kc) {
            uint32_t pah[4] = {aph[2 * kc][0], aph[2 * kc][1],
                               aph[2 * kc + 1][0], aph[2 * kc + 1][1]};
            uint32_t pal[4] = {apl[2 * kc][0], apl[2 * kc][1],
                               apl[2 * kc + 1][0], apl[2 * kc + 1][1]};
            uint32_t vh2[8][2], vl2[8][2];
#pragma unroll
            for (int nt = 0; nt < 8; ++nt) {
                ldm_x2t(vh2[nt], stbVH + kc * (16 * 144) + nt * 16);
                ldm_x2t(vl2[nt], stbVL + kc * (16 * 144) + nt * 16);
            }
#pragma unroll
            for (int nt = 0; nt < 8; ++nt)
                mma_bf16(ofr[nt], pah, vh2[nt][0], vh2[nt][1]);
#pragma unroll
            for (int nt = 0; nt < 8; ++nt)
                mma_bf16(ofr[nt], pah, vl2[nt][0], vl2[nt][1]);
#pragma unroll
            for (int nt = 0; nt < 8; ++nt)
                mma_bf16(ofr[nt], pal, vh2[nt][0], vh2[nt][1]);
        }
    }
#undef KV_ISSUE

    // Epilogue: normalize, split-write attention output
    float inv0 = 1.f / l0, inv1 = 1.f / l1;
    size_t row0 = (size_t)(qrow0 * BATCH + b) * (DMODEL / 2);
    size_t row1 = (size_t)(qrow1 * BATCH + b) * (DMODEL / 2);
#pragma unroll
    for (int nt = 0; nt < 8; ++nt) {
        int pcol = h * 32 + nt * 4 + q4;
        uint32_t hi, lo;
        bsplit2(ofr[nt][0] * inv0, ofr[nt][1] * inv0, hi, lo);
        ((uint32_t*)Oh)[row0 + pcol] = hi;
        ((uint32_t*)Ol)[row0 + pcol] = lo;
        bsplit2(ofr[nt][2] * inv1, ofr[nt][3] * inv1, hi, lo);
        ((uint32_t*)Oh)[row1 + pcol] = hi;
        ((uint32_t*)Ol)[row1 + pcol] = lo;
    }
}

// ---------------------------------------------------------------------------
extern "C" void kernel_launch(void* const* d_in, const int* in_sizes, int n_in,
                              void* d_out, int out_size)
{
    const float* x     = (const float*)d_in[0];   // [S,B,D]
    const float* w_qkv = (const float*)d_in[1];   // [3D,D]
    const float* w_out = (const float*)d_in[2];   // [D,D]
    const float* b_out = (const float*)d_in[3];   // [D]
    float* out = (float*)d_out;

    __nv_bfloat16 *xh, *xl, *wqh, *wql, *woh, *wol, *qkvh, *qkvl, *ah, *al;
    cudaGetSymbolAddress((void**)&xh,   g_xh);
    cudaGetSymbolAddress((void**)&xl,   g_xl);
    cudaGetSymbolAddress((void**)&wqh,  g_wqh);
    cudaGetSymbolAddress((void**)&wql,  g_wql);
    cudaGetSymbolAddress((void**)&woh,  g_woh);
    cudaGetSymbolAddress((void**)&wol,  g_wol);
    cudaGetSymbolAddress((void**)&qkvh, g_qkvh);
    cudaGetSymbolAddress((void**)&qkvl, g_qkvl);
    cudaGetSymbolAddress((void**)&ah,   g_ah);
    cudaGetSymbolAddress((void**)&al,   g_al);

    cudaFuncSetAttribute(gemm_bf16x3,
                         cudaFuncAttributeMaxDynamicSharedMemorySize, G_SMEM_BYTES);
    cudaFuncSetAttribute(attn_bf16,
                         cudaFuncAttributeMaxDynamicSharedMemorySize, ATT_SMEM_BYTES);

    // 0) Split inputs to bf16 hi/lo
    {
        int n1 = MROWS * DMODEL;        // x
        int n2 = 3 * DMODEL * DMODEL;   // w_qkv
        int n3 = DMODEL * DMODEL;       // w_out
        split_kernel<<<(n1 / 4 + 255) / 256, 256>>>(x, xh, xl, n1);
        split_kernel<<<(n2 / 4 + 255) / 256, 256>>>(w_qkv, wqh, wql, n2);
        split_kernel<<<(n3 / 4 + 255) / 256, 256>>>(w_out, woh, wol, n3);
    }

    // 1) QKV projection -> split qkv (Q cols scaled by 0.125)
    gemm_bf16x3<<<dim3(3 * DMODEL / 64, MROWS / 128), 128, G_SMEM_BYTES>>>(
        xh, xl, wqh, wql, nullptr, nullptr, qkvh, qkvl,
        MROWS, 3 * DMODEL, DMODEL, DMODEL);

    // 2) Causal flash attention -> split attention output
    attn_bf16<<<dim3(S_LEN / 64, BATCH * NH), 128, ATT_SMEM_BYTES>>>(
        qkvh, qkvl, ah, al);

    // 3) Output projection + bias -> fp32 out
    gemm_bf16x3<<<dim3(DMODEL / 64, MROWS / 128), 128, G_SMEM_BYTES>>>(
        ah, al, woh, wol, b_out, out, nullptr, nullptr,
        MROWS, DMODEL, DMODEL, 0);
}

// round 17
// speedup vs baseline: 2.0965x; 1.3265x over previous
#include <cuda_runtime.h>
#include <cuda_fp16.h>
#include <math.h>
#include <stdint.h>

// Problem constants
#define S_LEN 2048
#define BATCH 2
#define DMODEL 1024
#define NH 16
#define DKH 64
#define MROWS (S_LEN * BATCH)   // 4096

// ---------------------------------------------------------------------------
// Scratch (allocation-free rule: __device__ globals).
// A-operands: fp16 split pairs (hi+lo, exact to ~2^-22).
// B-operands (weights): single fp16 (error ~2^-12).
// ---------------------------------------------------------------------------
__device__ __half g_xh[(size_t)MROWS * DMODEL];
__device__ __half g_xl[(size_t)MROWS * DMODEL];
__device__ __half g_wq[(size_t)3 * DMODEL * DMODEL];
__device__ __half g_wo[(size_t)DMODEL * DMODEL];
__device__ __half g_qkvh[(size_t)MROWS * 3 * DMODEL];
__device__ __half g_qkvl[(size_t)MROWS * 3 * DMODEL];
__device__ __half g_ah[(size_t)MROWS * DMODEL];
__device__ __half g_al[(size_t)MROWS * DMODEL];

// ---------------------------------------------------------------------------
// Helpers
// ---------------------------------------------------------------------------
__device__ __forceinline__ uint32_t smem_u32(const void* p) {
    uint32_t a;
    asm("{ .reg .u64 t; cvta.to.shared.u64 t, %1; cvt.u32.u64 %0, t; }"
        : "=r"(a) : "l"(p));
    return a;
}

// split (x,y) -> packed fp16x2 hi + packed fp16x2 lo
__device__ __forceinline__ void hsplit2(float x, float y, uint32_t& hi, uint32_t& lo) {
    __half hx = __float2half_rn(x);
    __half hy = __float2half_rn(y);
    __half lx = __float2half_rn(x - __half2float(hx));
    __half ly = __float2half_rn(y - __half2float(hy));
    hi = (uint32_t)__half_as_ushort(hx) | ((uint32_t)__half_as_ushort(hy) << 16);
    lo = (uint32_t)__half_as_ushort(lx) | ((uint32_t)__half_as_ushort(ly) << 16);
}
__device__ __forceinline__ uint32_t hpack2(float x, float y) {
    return (uint32_t)__half_as_ushort(__float2half_rn(x))
         | ((uint32_t)__half_as_ushort(__float2half_rn(y)) << 16);
}

// m16n8k16 fp16 mma, D (f32) += A * B
__device__ __forceinline__ void mma_fp16(float* d, const uint32_t* a,
                                         uint32_t b0, uint32_t b1) {
    asm volatile(
        "mma.sync.aligned.m16n8k16.row.col.f32.f16.f16.f32 "
        "{%0,%1,%2,%3},{%4,%5,%6,%7},{%8,%9},{%0,%1,%2,%3};"
        : "+f"(d[0]), "+f"(d[1]), "+f"(d[2]), "+f"(d[3])
        : "r"(a[0]), "r"(a[1]), "r"(a[2]), "r"(a[3]), "r"(b0), "r"(b1));
}

__device__ __forceinline__ void ldm_x4(uint32_t* r, uint32_t addr) {
    asm volatile(
        "ldmatrix.sync.aligned.m8n8.x4.shared.b16 {%0,%1,%2,%3}, [%4];"
        : "=r"(r[0]), "=r"(r[1]), "=r"(r[2]), "=r"(r[3]) : "r"(addr));
}
__device__ __forceinline__ void ldm_x2(uint32_t* r, uint32_t addr) {
    asm volatile(
        "ldmatrix.sync.aligned.m8n8.x2.shared.b16 {%0,%1}, [%2];"
        : "=r"(r[0]), "=r"(r[1]) : "r"(addr));
}
__device__ __forceinline__ void ldm_x2t(uint32_t* r, uint32_t addr) {
    asm volatile(
        "ldmatrix.sync.aligned.m8n8.x2.trans.shared.b16 {%0,%1}, [%2];"
        : "=r"(r[0]), "=r"(r[1]) : "r"(addr));
}

__device__ __forceinline__ void cpasync16(uint32_t dst, const void* src) {
    asm volatile("cp.async.cg.shared.global [%0], [%1], 16;" :: "r"(dst), "l"(src));
}
__device__ __forceinline__ void cp_commit() {
    asm volatile("cp.async.commit_group;" ::: "memory");
}
template<int N> __device__ __forceinline__ void cp_wait() {
    asm volatile("cp.async.wait_group %0;" :: "n"(N) : "memory");
}

// ---------------------------------------------------------------------------
// Kernels: elementwise fp32 -> fp16 split / round
// ---------------------------------------------------------------------------
__global__ __launch_bounds__(256) void split_kernel(
    const float* __restrict__ in, __half* __restrict__ h,
    __half* __restrict__ l, int n)
{
    int i4 = (blockIdx.x * 256 + threadIdx.x) * 4;
    if (i4 >= n) return;
    float4 v = *(const float4*)(in + i4);
    uint32_t h0, l0, h1, l1;
    hsplit2(v.x, v.y, h0, l0);
    hsplit2(v.z, v.w, h1, l1);
    *(uint2*)((char*)h + (size_t)i4 * 2) = make_uint2(h0, h1);
    *(uint2*)((char*)l + (size_t)i4 * 2) = make_uint2(l0, l1);
}

__global__ __launch_bounds__(256) void round_kernel(
    const float* __restrict__ in, __half* __restrict__ h, int n)
{
    int i4 = (blockIdx.x * 256 + threadIdx.x) * 4;
    if (i4 >= n) return;
    float4 v = *(const float4*)(in + i4);
    *(uint2*)((char*)h + (size_t)i4 * 2) =
        make_uint2(hpack2(v.x, v.y), hpack2(v.z, v.w));
}

// ---------------------------------------------------------------------------
// fp16 2-term GEMM: C[m,n] = sum_k A[m,k]*B[n,k] (+bias)
// A split (Ah+Al), B single fp16. acc += Ah*B; acc += Al*B  (2 mma sweeps).
// BM=128, BN=64, BK=32, 128 threads (4 warps 2x2, warp tile 64x32).
// 2-stage cp.async, 3 CTAs/SM, 1 sync/iter.
// Rows in smem: 32 fp16 (64B) + 16B pad = 80B stride (ldmatrix conflict-free).
// Stage: Ah@0 (10240) | Al@10240 | Bh@20480 (5120).  25600B/stage.
// ---------------------------------------------------------------------------
#define G_STAGE_BYTES 25600
#define G_SMEM_BYTES (2 * G_STAGE_BYTES)   // 51200

__global__ __launch_bounds__(128, 3) void gemm_fp16x2(
    const __half* __restrict__ Ah, const __half* __restrict__ Al,
    const __half* __restrict__ Bh,
    const float* __restrict__ bias, float* __restrict__ Cf,
    __half* __restrict__ Ch, __half* __restrict__ Cl,
    int M, int N, int K, int qscaleCols)
{
    extern __shared__ char smem[];
    const uint32_t sbase = smem_u32(smem);
    const int tid  = threadIdx.x;
    const int lane = tid & 31;
    const int warp = tid >> 5;
    const int g    = lane >> 2;
    const int q4   = lane & 3;
    const int wm   = warp >> 1;       // 0..1 (64 rows each)
    const int wn   = warp & 1;        // 0..1 (32 cols each)
    const int mBase = blockIdx.y * 128;
    const int nBase = blockIdx.x * 64;

    float acc[4][4][4];
#pragma unroll
    for (int i = 0; i < 4; ++i)
#pragma unroll
        for (int j = 0; j < 4; ++j)
#pragma unroll
            for (int c = 0; c < 4; ++c) acc[i][j][c] = 0.f;

    const int lj = lane >> 3, l7 = lane & 7;
    const uint32_t aRowBase = (uint32_t)(wm * 64 + (lj & 1) * 8 + l7) * 80
                              + (uint32_t)(lj >> 1) * 16;
    const uint32_t bRowBase = (uint32_t)(wn * 32 + (lj >> 1) * 8 + l7) * 80
                              + (uint32_t)(lj & 1) * 16;

    const int NT = K / 32;            // 32

#define G_ISSUE(ITER) do {                                                      \
    int s_ = (ITER) & 1;                                                        \
    int k0_ = (ITER) * 32;                                                      \
    uint32_t stb_ = sbase + s_ * G_STAGE_BYTES;                                 \
    _Pragma("unroll")                                                           \
    for (int j_ = 0; j_ < 4; ++j_) {  /* Ah then Al */                          \
        int cid_ = tid + j_ * 128;                                              \
        int row_ = cid_ >> 2, ch_ = cid_ & 3;                                   \
        cpasync16(stb_ + row_ * 80 + ch_ * 16,                                  \
                  (const char*)(Ah + (size_t)(mBase + row_) * K + k0_) + ch_ * 16); \
        cpasync16(stb_ + 10240 + row_ * 80 + ch_ * 16,                          \
                  (const char*)(Al + (size_t)(mBase + row_) * K + k0_) + ch_ * 16); \
    }                                                                           \
    _Pragma("unroll")                                                           \
    for (int j_ = 0; j_ < 2; ++j_) {  /* Bh */                                  \
        int cid_ = tid + j_ * 128;                                              \
        int row_ = cid_ >> 2, ch_ = cid_ & 3;                                   \
        cpasync16(stb_ + 20480 + row_ * 80 + ch_ * 16,                          \
                  (const char*)(Bh + (size_t)(nBase + row_) * K + k0_) + ch_ * 16); \
    }                                                                           \
} while (0)

    G_ISSUE(0); cp_commit();

    for (int it = 0; it < NT; ++it) {
        cp_wait<0>();
        __syncthreads();
        if (it + 1 < NT) { G_ISSUE(it + 1); cp_commit(); }

        const uint32_t stb = sbase + (it & 1) * G_STAGE_BYTES;

#pragma unroll
        for (int ks = 0; ks < 2; ++ks) {
            const uint32_t kk = ks * 32;
            uint32_t ah[4][4], al[4][4];
#pragma unroll
            for (int mf = 0; mf < 4; ++mf) {
                ldm_x4(ah[mf], stb + aRowBase + mf * (16 * 80) + kk);
                ldm_x4(al[mf], stb + 10240 + aRowBase + mf * (16 * 80) + kk);
            }
            uint32_t bh[4][2];
#pragma unroll
            for (int np = 0; np < 2; ++np) {
                uint32_t r[4];
                ldm_x4(r, stb + 20480 + bRowBase + np * (16 * 80) + kk);
                bh[np * 2][0] = r[0]; bh[np * 2][1] = r[1];
                bh[np * 2 + 1][0] = r[2]; bh[np * 2 + 1][1] = r[3];
            }
            // 2 de-chained sweeps (acc reuse distance = 16 mmas)
#pragma unroll
            for (int mf = 0; mf < 4; ++mf)
#pragma unroll
                for (int nf = 0; nf < 4; ++nf)
                    mma_fp16(acc[mf][nf], ah[mf], bh[nf][0], bh[nf][1]);
#pragma unroll
            for (int mf = 0; mf < 4; ++mf)
#pragma unroll
                for (int nf = 0; nf < 4; ++nf)
                    mma_fp16(acc[mf][nf], al[mf], bh[nf][0], bh[nf][1]);
        }
    }
#undef G_ISSUE

    // Epilogue
    const int Np = N >> 1;
#pragma unroll
    for (int mf = 0; mf < 4; ++mf) {
        int r0 = mBase + wm * 64 + mf * 16 + g;
        int r1 = r0 + 8;
#pragma unroll
        for (int nf = 0; nf < 4; ++nf) {
            int col = nBase + wn * 32 + nf * 8 + 2 * q4;
            if (Cf) {
                float bx = bias ? bias[col] : 0.f;
                float by = bias ? bias[col + 1] : 0.f;
                *(float2*)(Cf + (size_t)r0 * N + col) =
                    make_float2(acc[mf][nf][0] + bx, acc[mf][nf][1] + by);
                *(float2*)(Cf + (size_t)r1 * N + col) =
                    make_float2(acc[mf][nf][2] + bx, acc[mf][nf][3] + by);
            } else {
                float sc = (col < qscaleCols) ? 0.125f : 1.f;
                uint32_t hi, lo;
                hsplit2(acc[mf][nf][0] * sc, acc[mf][nf][1] * sc, hi, lo);
                ((uint32_t*)Ch)[(size_t)r0 * Np + (col >> 1)] = hi;
                ((uint32_t*)Cl)[(size_t)r0 * Np + (col >> 1)] = lo;
                hsplit2(acc[mf][nf][2] * sc, acc[mf][nf][3] * sc, hi, lo);
                ((uint32_t*)Ch)[(size_t)r1 * Np + (col >> 1)] = hi;
                ((uint32_t*)Cl)[(size_t)r1 * Np + (col >> 1)] = lo;
            }
        }
    }
}

// ---------------------------------------------------------------------------
// Flash attention, fp16 2-term mma. Q split (qh+ql), K/V single fp16
// (read from the hi array only). P split in registers.
// grid (S/64, B*H), 128 threads. 2-stage cp.async KV pipeline, qt DESCENDING.
// smem (u32): QH[64x36] | QL | 2 stages x (KH,VH each 64x36) = 55296B total.
// ---------------------------------------------------------------------------
#define A_QL 2304
#define A_ST 4608
#define A_STAGE_U32 4608
#define ATT_SMEM_BYTES ((A_ST + 2 * A_STAGE_U32) * 4)   // 55296

__global__ __launch_bounds__(128) void attn_fp16(
    const __half* __restrict__ QKVh, const __half* __restrict__ QKVl,
    __half* __restrict__ Oh, __half* __restrict__ Ol)
{
    extern __shared__ uint32_t sm4[];
    const uint32_t sbase = smem_u32(sm4);
    const int qt  = gridDim.x - 1 - blockIdx.x;   // heavy tiles first
    const int bh  = blockIdx.y;
    const int h   = bh & 15;
    const int b   = bh >> 4;
    const int tid = threadIdx.x;
    const int w    = tid >> 5;
    const int lane = tid & 31;
    const int g    = lane >> 2;
    const int q4   = lane & 3;
    const int qBase = qt * 64;

#define KV_ISSUE(KT) do {                                                       \
    int s_ = (KT) & 1;                                                          \
    uint32_t stb_ = sbase + (A_ST + s_ * A_STAGE_U32) * 4;                      \
    _Pragma("unroll")                                                           \
    for (int j_ = 0; j_ < 4; ++j_) {                                            \
        int id_ = tid + j_ * 128;                                               \
        int row_ = id_ >> 3, ch_ = id_ & 7;                                     \
        size_t ks_ = (size_t)(((KT) * 64 + row_) * BATCH + b) * (3 * DMODEL)    \
                     + DMODEL + h * DKH;                                        \
        size_t vs_ = ks_ + DMODEL;                                              \
        cpasync16(stb_ + row_ * 144 + ch_ * 16, (const char*)(QKVh + ks_) + ch_ * 16); \
        cpasync16(stb_ + 9216 + row_ * 144 + ch_ * 16, (const char*)(QKVh + vs_) + ch_ * 16); \
    }                                                                           \
} while (0)

    KV_ISSUE(0); cp_commit();

    // Load Q tile (split, already scaled): 64 rows x 128B per array
#pragma unroll
    for (int j = 0; j < 4; ++j) {
        int id = tid + j * 128;
        int row = id >> 3, ch = id & 7;
        size_t src = (size_t)((qBase + row) * BATCH + b) * (3 * DMODEL) + h * DKH;
        uint4 vh = *(const uint4*)((const char*)(QKVh + src) + ch * 16);
        uint4 vl = *(const uint4*)((const char*)(QKVl + src) + ch * 16);
        *(uint4*)((char*)sm4 + row * 144 + ch * 16) = vh;
        *(uint4*)((char*)sm4 + A_QL * 4 + row * 144 + ch * 16) = vl;
    }
    __syncthreads();

    // Q fragments
    uint32_t qh[4][4], ql[4][4];
    {
        int r0 = (w * 16 + g) * 36;
        int r1 = r0 + 288;
#pragma unroll
        for (int kc = 0; kc < 4; ++kc) {
            qh[kc][0] = sm4[r0 + kc * 8 + q4];
            qh[kc][1] = sm4[r1 + kc * 8 + q4];
            qh[kc][2] = sm4[r0 + kc * 8 + 4 + q4];
            qh[kc][3] = sm4[r1 + kc * 8 + 4 + q4];
            ql[kc][0] = sm4[A_QL + r0 + kc * 8 + q4];
            ql[kc][1] = sm4[A_QL + r1 + kc * 8 + q4];
            ql[kc][2] = sm4[A_QL + r0 + kc * 8 + 4 + q4];
            ql[kc][3] = sm4[A_QL + r1 + kc * 8 + 4 + q4];
        }
    }

    float ofr[8][4];
#pragma unroll
    for (int nt = 0; nt < 8; ++nt)
#pragma unroll
        for (int c = 0; c < 4; ++c) ofr[nt][c] = 0.f;

    float m0 = -INFINITY, m1 = -INFINITY, l0 = 0.f, l1 = 0.f;
    const int qrow0 = qBase + w * 16 + g;
    const int qrow1 = qrow0 + 8;

    // ldmatrix per-lane address terms
    const int l7  = lane & 7;
    const int l15 = lane & 15;
    const uint32_t kLane = (uint32_t)l7 * 144 + (uint32_t)((lane >> 3) & 1) * 16;
    const uint32_t vLane = (uint32_t)l15 * 144;

    for (int kt = 0; kt <= qt; ++kt) {
        cp_wait<0>();
        __syncthreads();
        if (kt < qt) { KV_ISSUE(kt + 1); cp_commit(); }

        const uint32_t stb = sbase + (A_ST + (kt & 1) * A_STAGE_U32) * 4;
        const uint32_t stbKH = stb + kLane;
        const uint32_t stbVH = stb + 9216 + vLane;

        // S = Q K^T (2 de-chained sweeps per kc)
        float sfr[8][4];
#pragma unroll
        for (int nt = 0; nt < 8; ++nt)
#pragma unroll
            for (int c = 0; c < 4; ++c) sfr[nt][c] = 0.f;

#pragma unroll
        for (int kc = 0; kc < 4; ++kc) {
            uint32_t kh2[8][2];
#pragma unroll
            for (int nt = 0; nt < 8; ++nt)
                ldm_x2(kh2[nt], stbKH + nt * (8 * 144) + kc * 32);
#pragma unroll
            for (int nt = 0; nt < 8; ++nt)
                mma_fp16(sfr[nt], qh[kc], kh2[nt][0], kh2[nt][1]);
#pragma unroll
            for (int nt = 0; nt < 8; ++nt)
                mma_fp16(sfr[nt], ql[kc], kh2[nt][0], kh2[nt][1]);
        }

        // Causal mask (diagonal tile only)
        if (kt == qt) {
#pragma unroll
            for (int nt = 0; nt < 8; ++nt) {
                int key = kt * 64 + nt * 8 + 2 * q4;
                if (key     > qrow0) sfr[nt][0] = -INFINITY;
                if (key + 1 > qrow0) sfr[nt][1] = -INFINITY;
                if (key     > qrow1) sfr[nt][2] = -INFINITY;
                if (key + 1 > qrow1) sfr[nt][3] = -INFINITY;
            }
        }

        // Online softmax
        float mx0 = -INFINITY, mx1 = -INFINITY;
#pragma unroll
        for (int nt = 0; nt < 8; ++nt) {
            mx0 = fmaxf(mx0, fmaxf(sfr[nt][0], sfr[nt][1]));
            mx1 = fmaxf(mx1, fmaxf(sfr[nt][2], sfr[nt][3]));
        }
        mx0 = fmaxf(mx0, __shfl_xor_sync(0xffffffffu, mx0, 1));
        mx0 = fmaxf(mx0, __shfl_xor_sync(0xffffffffu, mx0, 2));
        mx1 = fmaxf(mx1, __shfl_xor_sync(0xffffffffu, mx1, 1));
        mx1 = fmaxf(mx1, __shfl_xor_sync(0xffffffffu, mx1, 2));

        float mn0 = fmaxf(m0, mx0), mn1 = fmaxf(m1, mx1);
        float cr0 = __expf(m0 - mn0), cr1 = __expf(m1 - mn1);
        l0 *= cr0; l1 *= cr1;
        m0 = mn0;  m1 = mn1;

        // exp -> P fragments directly in registers (fp16 split)
        uint32_t aph[8][2], apl[8][2];
        float ps0 = 0.f, ps1 = 0.f;
#pragma unroll
        for (int nt = 0; nt < 8; ++nt) {
            ofr[nt][0] *= cr0; ofr[nt][1] *= cr0;
            ofr[nt][2] *= cr1; ofr[nt][3] *= cr1;
            float p0 = __expf(sfr[nt][0] - m0);
            float p1 = __expf(sfr[nt][1] - m0);
            float p2 = __expf(sfr[nt][2] - m1);
            float p3 = __expf(sfr[nt][3] - m1);
            ps0 += p0 + p1; ps1 += p2 + p3;
            hsplit2(p0, p1, aph[nt][0], apl[nt][0]);
            hsplit2(p2, p3, aph[nt][1], apl[nt][1]);
        }
        ps0 += __shfl_xor_sync(0xffffffffu, ps0, 1);
        ps0 += __shfl_xor_sync(0xffffffffu, ps0, 2);
        ps1 += __shfl_xor_sync(0xffffffffu, ps1, 1);
        ps1 += __shfl_xor_sync(0xffffffffu, ps1, 2);
        l0 += ps0; l1 += ps1;

        // O += P V  (V fragments via ldmatrix.trans on K-major V rows)
#pragma unroll
        for (int kc = 0; kc < 4; ++kc) {
            uint32_t pah[4] = {aph[2 * kc][0], aph[2 * kc][1],
                               aph[2 * kc + 1][0], aph[2 * kc + 1][1]};
            uint32_t pal[4] = {apl[2 * kc][0], apl[2 * kc][1],
                               apl[2 * kc + 1][0], apl[2 * kc + 1][1]};
            uint32_t vh2[8][2];
#pragma unroll
            for (int nt = 0; nt < 8; ++nt)
                ldm_x2t(vh2[nt], stbVH + kc * (16 * 144) + nt * 16);
#pragma unroll
            for (int nt = 0; nt < 8; ++nt)
                mma_fp16(ofr[nt], pah, vh2[nt][0], vh2[nt][1]);
#pragma unroll
            for (int nt = 0; nt < 8; ++nt)
                mma_fp16(ofr[nt], pal, vh2[nt][0], vh2[nt][1]);
        }
    }
#undef KV_ISSUE

    // Epilogue: normalize, split-write attention output
    float inv0 = 1.f / l0, inv1 = 1.f / l1;
    size_t row0 = (size_t)(qrow0 * BATCH + b) * (DMODEL / 2);
    size_t row1 = (size_t)(qrow1 * BATCH + b) * (DMODEL / 2);
#pragma unroll
    for (int nt = 0; nt < 8; ++nt) {
        int pcol = h * 32 + nt * 4 + q4;
        uint32_t hi, lo;
        hsplit2(ofr[nt][0] * inv0, ofr[nt][1] * inv0, hi, lo);
        ((uint32_t*)Oh)[row0 + pcol] = hi;
        ((uint32_t*)Ol)[row0 + pcol] = lo;
        hsplit2(ofr[nt][2] * inv1, ofr[nt][3] * inv1, hi, lo);
        ((uint32_t*)Oh)[row1 + pcol] = hi;
        ((uint32_t*)Ol)[row1 + pcol] = lo;
    }
}

// ---------------------------------------------------------------------------
extern "C" void kernel_launch(void* const* d_in, const int* in_sizes, int n_in,
                              void* d_out, int out_size)
{
    const float* x     = (const float*)d_in[0];   // [S,B,D]
    const float* w_qkv = (const float*)d_in[1];   // [3D,D]
    const float* w_out = (const float*)d_in[2];   // [D,D]
    const float* b_out = (const float*)d_in[3];   // [D]
    float* out = (float*)d_out;

    __half *xh, *xl, *wq, *wo, *qkvh, *qkvl, *ah, *al;
    cudaGetSymbolAddress((void**)&xh,   g_xh);
    cudaGetSymbolAddress((void**)&xl,   g_xl);
    cudaGetSymbolAddress((void**)&wq,   g_wq);
    cudaGetSymbolAddress((void**)&wo,   g_wo);
    cudaGetSymbolAddress((void**)&qkvh, g_qkvh);
    cudaGetSymbolAddress((void**)&qkvl, g_qkvl);
    cudaGetSymbolAddress((void**)&ah,   g_ah);
    cudaGetSymbolAddress((void**)&al,   g_al);

    cudaFuncSetAttribute(gemm_fp16x2,
                         cudaFuncAttributeMaxDynamicSharedMemorySize, G_SMEM_BYTES);
    cudaFuncSetAttribute(attn_fp16,
                         cudaFuncAttributeMaxDynamicSharedMemorySize, ATT_SMEM_BYTES);

    // 0) Convert inputs: activations split, weights rounded
    {
        int n1 = MROWS * DMODEL;        // x
        int n2 = 3 * DMODEL * DMODEL;   // w_qkv
        int n3 = DMODEL * DMODEL;       // w_out
        split_kernel<<<(n1 / 4 + 255) / 256, 256>>>(x, xh, xl, n1);
        round_kernel<<<(n2 / 4 + 255) / 256, 256>>>(w_qkv, wq, n2);
        round_kernel<<<(n3 / 4 + 255) / 256, 256>>>(w_out, wo, n3);
    }

    // 1) QKV projection -> split qkv (Q cols scaled by 0.125)
    gemm_fp16x2<<<dim3(3 * DMODEL / 64, MROWS / 128), 128, G_SMEM_BYTES>>>(
        xh, xl, wq, nullptr, nullptr, qkvh, qkvl,
        MROWS, 3 * DMODEL, DMODEL, DMODEL);

    // 2) Causal flash attention -> split attention output
    attn_fp16<<<dim3(S_LEN / 64, BATCH * NH), 128, ATT_SMEM_BYTES>>>(
        qkvh, qkvl, ah, al);

    // 3) Output projection + bias -> fp32 out
    gemm_fp16x2<<<dim3(DMODEL / 64, MROWS / 128), 128, G_SMEM_BYTES>>>(
        ah, al, wo, b_out, out, nullptr, nullptr,
        MROWS, DMODEL, DMODEL, 0);
}